// round 12
// baseline (speedup 1.0000x reference)
#include <cuda_runtime.h>
#include <cuda_fp16.h>
#include <cstdint>

#define B_  4
#define C_  512
#define CI_ 256
#define N_  4096
#define EPS_ 1e-5f
#define ZSCALE 64.0f
#define SLICES 16

// ------------------------- device scratch (no allocs) -------------------------
__device__ half vT_h[B_ * N_ * C_],  vT_l[B_ * N_ * C_];     // 16 MB each
__device__ half th_h[B_ * N_ * CI_], th_l[B_ * N_ * CI_];    //  8 MB each
__device__ half ph_h[B_ * CI_ * N_];                          //  8 MB
__device__ half g_h [B_ * CI_ * N_], g_l [B_ * CI_ * N_];    //  8 MB each
__device__ half y_h [B_ * N_ * CI_];                          //  8 MB
__device__ half Wph_h[CI_ * C_], Wph_l[CI_ * C_];
__device__ half Wg_h [CI_ * C_], Wg_l [CI_ * C_];
__device__ half Wth_h[CI_ * C_];
__device__ half Ww_h [C_ * CI_], Ww_l [C_ * CI_];
__device__ float Wy_buf[B_ * C_ * N_];                        // 32 MB
__device__ float Zt_buf[B_ * CI_ * CI_];                      //  1 MB
__device__ float bn_sum[C_];
__device__ float bn_sumsq[C_];

// ------------------------------- GEMM config ----------------------------------
// CTA tile 128(M) x 64(N) x 32(K), 256 threads (8 warps, 4x2, 32x32 each).
// All operands pre-split planar fp16; staging = pure LDG.128/STS.128.
#define PITCH 40
#define ROWB  (PITCH * 2)
#define A_TILE_B 10240
#define B_TILE_B 5120
#define A_TILE_H (A_TILE_B / 2)
#define OFF_BH   (2 * A_TILE_B)
#define BUF_BYTES (2 * A_TILE_B + B_TILE_B)        // 25600
#define SMEM_GEMM_BYTES (2 * BUF_BYTES + 1024)     // 52224

__device__ __forceinline__ uint32_t smem_u32(const void* p) {
    uint32_t a;
    asm("{ .reg .u64 t; cvta.to.shared.u64 t, %1; cvt.u32.u64 %0, t; }" : "=r"(a) : "l"(p));
    return a;
}
__device__ __forceinline__ void ldm_x4(uint32_t* r, uint32_t addr) {
    asm volatile("ldmatrix.sync.aligned.m8n8.x4.shared.b16 {%0,%1,%2,%3}, [%4];"
                 : "=r"(r[0]), "=r"(r[1]), "=r"(r[2]), "=r"(r[3]) : "r"(addr));
}
__device__ __forceinline__ void mma16816(float* c, const uint32_t* a, const uint32_t* b) {
    asm volatile(
        "mma.sync.aligned.m16n8k16.row.col.f32.f16.f16.f32 "
        "{%0,%1,%2,%3}, {%4,%5,%6,%7}, {%8,%9}, {%0,%1,%2,%3};"
        : "+f"(c[0]), "+f"(c[1]), "+f"(c[2]), "+f"(c[3])
        : "r"(a[0]), "r"(a[1]), "r"(a[2]), "r"(a[3]), "r"(b[0]), "r"(b[1]));
}
// B fp32 fallback: hi plane only
__device__ __forceinline__ void store_hi(half* base, int idx, float4 x) {
    *(half2*)&base[idx]     = __floats2half2_rn(x.x, x.y);
    *(half2*)&base[idx + 2] = __floats2half2_rn(x.z, x.w);
}

// ------------------------------------------------------------------------------
// D[M,Nt] = alpha * (Ah+Al)[M,K] @ Bop[Nt,K]^T + biasM + biasN
// A pre-split planar fp16 (hi, lo), K-contiguous, stride ldA halves.
// B_F16=1: B = pre-split hi plane, stride ldB halves. B_F16=0: B fp32, ldB floats.
// OUT_MODE: 0 = fp32 (Df), 1 = hi+lo halves (Dh, Dl), 2 = hi only (Dh).
// 128x64x32 tiles, 256 thr, 2 CTAs/SM. grid=(Nt/64, M/128, nBatch*nSlices).
// ------------------------------------------------------------------------------
template <int OUT_MODE, bool B_F16, bool BN_ACC, bool ATOMIC_OUT>
__global__ __launch_bounds__(256, 2)
void gemm_h2(const half* __restrict__ Ah, const half* __restrict__ Al,
             const half* __restrict__ Bh, const float* __restrict__ Bf,
             float* __restrict__ Df, half* __restrict__ Dh, half* __restrict__ Dl,
             const float* __restrict__ biasM, const float* __restrict__ biasN,
             int M, int Nt, int K, int ldA, int ldB, float alpha,
             int nSlices,
             long sbA, long slA, long sbB, long slB, long sbD, long slD)
{
    extern __shared__ char smem[];
    half*  sh  = (half*)smem;
    float* sBM = (float*)(smem + 2 * BUF_BYTES);
    float* sBN = sBM + 128;
    const uint32_t sbu = smem_u32(sh);

    const int tid = threadIdx.x;
    const int bx = blockIdx.x, by = blockIdx.y, bz = blockIdx.z;
    const int bb = bz / nSlices;
    const int ss = bz % nSlices;
    const long aoff = bb * sbA + ss * slA + (long)(by * 128) * ldA;
    Ah += aoff;  Al += aoff;
    if (B_F16) Bh += bb * sbB + ss * slB + (long)(bx * 64) * ldB;
    else       Bf += bb * sbB + ss * slB + (long)(bx * 64) * ldB;
    const long dOff = bb * sbD + ss * slD;

    if (tid < 128) sBM[tid] = biasM ? biasM[by * 128 + tid] : 0.f;
    if (tid < 64)  sBN[tid] = biasN ? biasN[bx * 64 + tid] : 0.f;

    const int nIter = K / 32;

    // A staging: thread covers rows ar, ar+64; 16B chunk col ac (halves)
    const int ar = tid >> 2;
    const int ac = (tid & 3) * 8;
    const half* pAh0 = Ah + (long)ar * ldA + ac;
    const half* pAh1 = pAh0 + 64L * ldA;
    const half* pAl0 = Al + (long)ar * ldA + ac;
    const half* pAl1 = pAl0 + 64L * ldA;
    const int iA0 = ar * PITCH + ac;
    const int iA1 = (ar + 64) * PITCH + ac;

    // B f16 staging: row tid>>2 (0..63), chunk ac
    const half* pBh = nullptr;
    int iB16 = 0;
    // B f32 staging (2 rows/thread)
    const int sf = tid & 7, sr = tid >> 3;
    const float* pBf0 = nullptr;
    const float* pBf1 = nullptr;
    int iBf0 = 0, iBf1 = 0;
    if (B_F16) {
        pBh = Bh + (long)(tid >> 2) * ldB + ac;
        iB16 = (tid >> 2) * PITCH + ac;
    } else {
        pBf0 = Bf + (long)sr * ldB + sf * 4;
        pBf1 = Bf + (long)(sr + 32) * ldB + sf * 4;
        iBf0 = sr * PITCH + sf * 4;
        iBf1 = (sr + 32) * PITCH + sf * 4;
    }

    uint4 a0, a1, l0, l1, b16 = {0, 0, 0, 0};
    float4 f0 = {0, 0, 0, 0}, f1 = {0, 0, 0, 0};
    a0 = *(const uint4*)pAh0; pAh0 += 32;
    a1 = *(const uint4*)pAh1; pAh1 += 32;
    l0 = *(const uint4*)pAl0; pAl0 += 32;
    l1 = *(const uint4*)pAl1; pAl1 += 32;
    if (B_F16) { b16 = *(const uint4*)pBh; pBh += 32; }
    else {
        f0 = *(const float4*)pBf0; pBf0 += 32;
        f1 = *(const float4*)pBf1; pBf1 += 32;
    }
    {
        half* Ab = sh;
        half* Bb = sh + OFF_BH / 2;
        *(uint4*)&Ab[iA0] = a0;
        *(uint4*)&Ab[iA1] = a1;
        *(uint4*)&Ab[A_TILE_H + iA0] = l0;
        *(uint4*)&Ab[A_TILE_H + iA1] = l1;
        if (B_F16) *(uint4*)&Bb[iB16] = b16;
        else { store_hi(Bb, iBf0, f0); store_hi(Bb, iBf1, f1); }
    }
    __syncthreads();

    float acc[2][4][4];
#pragma unroll
    for (int mi = 0; mi < 2; ++mi)
#pragma unroll
        for (int ni = 0; ni < 4; ++ni)
#pragma unroll
            for (int q = 0; q < 4; ++q) acc[mi][ni][q] = 0.f;

    const int wid = tid >> 5, lid = tid & 31;
    const int wm = (wid >> 1) * 32;
    const int wn = (wid & 1) * 32;
    const int g = lid >> 2;
    const int t = lid & 3;

    const uint32_t laneA = (uint32_t)((lid & 15) * ROWB + (lid >> 4) * 16);
    const uint32_t laneB = (uint32_t)((((lid >> 4) * 8) + (lid & 7)) * ROWB
                                      + ((lid >> 3) & 1) * 16);
    const uint32_t aWarp = sbu + (uint32_t)(wm * ROWB) + laneA;
    const uint32_t bWarp = sbu + OFF_BH + (uint32_t)(wn * ROWB) + laneB;

    for (int it = 0; it < nIter; ++it) {
        const int buf = it & 1;
        const bool hasNext = (it + 1 < nIter);
        if (hasNext) {
            a0 = *(const uint4*)pAh0; pAh0 += 32;
            a1 = *(const uint4*)pAh1; pAh1 += 32;
            l0 = *(const uint4*)pAl0; pAl0 += 32;
            l1 = *(const uint4*)pAl1; pAl1 += 32;
            if (B_F16) { b16 = *(const uint4*)pBh; pBh += 32; }
            else {
                f0 = *(const float4*)pBf0; pBf0 += 32;
                f1 = *(const float4*)pBf1; pBf1 += 32;
            }
        }

        const uint32_t bo = (uint32_t)(buf * BUF_BYTES);
#pragma unroll
        for (int kk = 0; kk < 2; ++kk) {
            const uint32_t ko = (uint32_t)(kk * 32);
            uint32_t ah[2][4], al[2][4];
#pragma unroll
            for (int mi = 0; mi < 2; ++mi) {
                const uint32_t addr = aWarp + bo + (uint32_t)(mi * 16 * ROWB) + ko;
                ldm_x4(ah[mi], addr);
                ldm_x4(al[mi], addr + A_TILE_B);
            }
            uint32_t bh[2][4];
#pragma unroll
            for (int nb = 0; nb < 2; ++nb) {
                const uint32_t addr = bWarp + bo + (uint32_t)(nb * 16 * ROWB) + ko;
                ldm_x4(bh[nb], addr);
            }
#pragma unroll
            for (int mi = 0; mi < 2; ++mi)
#pragma unroll
                for (int ni = 0; ni < 4; ++ni)
                    mma16816(acc[mi][ni], ah[mi], &bh[ni >> 1][(ni & 1) * 2]);
#pragma unroll
            for (int mi = 0; mi < 2; ++mi)
#pragma unroll
                for (int ni = 0; ni < 4; ++ni)
                    mma16816(acc[mi][ni], al[mi], &bh[ni >> 1][(ni & 1) * 2]);
        }

        if (hasNext) {
            half* Ab = sh + (buf ^ 1) * (BUF_BYTES / 2);
            half* Bb = Ab + OFF_BH / 2;
            *(uint4*)&Ab[iA0] = a0;
            *(uint4*)&Ab[iA1] = a1;
            *(uint4*)&Ab[A_TILE_H + iA0] = l0;
            *(uint4*)&Ab[A_TILE_H + iA1] = l1;
            if (B_F16) *(uint4*)&Bb[iB16] = b16;
            else { store_hi(Bb, iBf0, f0); store_hi(Bb, iBf1, f1); }
        }
        __syncthreads();
    }

    // ---------------- epilogue ----------------
#pragma unroll
    for (int mi = 0; mi < 2; ++mi) {
        const int rowLoc = wm + mi * 16 + g;
        const int chan0 = by * 128 + rowLoc;
        const float bm0 = sBM[rowLoc], bm1 = sBM[rowLoc + 8];
        const long gr0 = dOff + (long)chan0 * Nt + bx * 64;
        const long gr1 = gr0 + 8L * Nt;
        float s0 = 0.f, q0 = 0.f, s1 = 0.f, q1 = 0.f;
#pragma unroll
        for (int ni = 0; ni < 4; ++ni) {
            const int col = wn + ni * 8 + t * 2;
            const float bn0 = sBN[col], bn1 = sBN[col + 1];
            float2 o0, o1;
            o0.x = alpha * acc[mi][ni][0] + bm0 + bn0;
            o0.y = alpha * acc[mi][ni][1] + bm0 + bn1;
            o1.x = alpha * acc[mi][ni][2] + bm1 + bn0;
            o1.y = alpha * acc[mi][ni][3] + bm1 + bn1;
            if (OUT_MODE == 0) {
                if (ATOMIC_OUT) {
                    atomicAdd(&Df[gr0 + col],     o0.x);
                    atomicAdd(&Df[gr0 + col + 1], o0.y);
                    atomicAdd(&Df[gr1 + col],     o1.x);
                    atomicAdd(&Df[gr1 + col + 1], o1.y);
                } else {
                    *(float2*)&Df[gr0 + col] = o0;
                    *(float2*)&Df[gr1 + col] = o1;
                }
            } else {
                half2 h0 = __floats2half2_rn(o0.x, o0.y);
                half2 h1 = __floats2half2_rn(o1.x, o1.y);
                *(half2*)&Dh[gr0 + col] = h0;
                *(half2*)&Dh[gr1 + col] = h1;
                if (OUT_MODE == 1) {
                    float2 v0 = __half22float2(h0);
                    float2 v1 = __half22float2(h1);
                    *(half2*)&Dl[gr0 + col] = __floats2half2_rn(o0.x - v0.x, o0.y - v0.y);
                    *(half2*)&Dl[gr1 + col] = __floats2half2_rn(o1.x - v1.x, o1.y - v1.y);
                }
            }
            if (BN_ACC) {
                s0 += o0.x + o0.y;  q0 += o0.x * o0.x + o0.y * o0.y;
                s1 += o1.x + o1.y;  q1 += o1.x * o1.x + o1.y * o1.y;
            }
        }
        if (BN_ACC) {
#pragma unroll
            for (int o = 1; o < 4; o <<= 1) {
                s0 += __shfl_xor_sync(0xFFFFFFFF, s0, o);
                q0 += __shfl_xor_sync(0xFFFFFFFF, q0, o);
                s1 += __shfl_xor_sync(0xFFFFFFFF, s1, o);
                q1 += __shfl_xor_sync(0xFFFFFFFF, q1, o);
            }
            if (t == 0) {
                atomicAdd(&bn_sum[chan0],       s0);
                atomicAdd(&bn_sumsq[chan0],     q0);
                atomicAdd(&bn_sum[chan0 + 8],   s1);
                atomicAdd(&bn_sumsq[chan0 + 8], q1);
            }
        }
    }
}

// ------------------------------------------------------------------------------
// v [B,C,N] fp32 -> vT hi/lo [B,N,C] halves
__global__ __launch_bounds__(256)
void transpose_split_kernel(const float* __restrict__ v,
                            half* __restrict__ hi, half* __restrict__ lo)
{
    __shared__ float tbuf[32][33];
    const int b = blockIdx.z;
    const int n0 = blockIdx.x * 32, c0 = blockIdx.y * 32;
    const int tx = threadIdx.x, ty = threadIdx.y;   // 32 x 8
#pragma unroll
    for (int i = 0; i < 4; ++i)
        tbuf[ty + 8 * i][tx] = v[((long)b * C_ + c0 + ty + 8 * i) * N_ + n0 + tx];
    __syncthreads();
#pragma unroll
    for (int i = 0; i < 4; ++i) {
        const float x = tbuf[tx][ty + 8 * i];
        const half h = __float2half_rn(x);
        const long o = ((long)b * N_ + n0 + ty + 8 * i) * C_ + c0 + tx;
        hi[o] = h;
        lo[o] = __float2half_rn(x - __half2float(h));
    }
}

// ------------------------------------------------------------------------------
// split 4 weight matrices to planar fp16 (Wth hi-only)
__global__ __launch_bounds__(256)
void prep_weights_kernel(const float* __restrict__ Wph, const float* __restrict__ Wg,
                         const float* __restrict__ Wth, const float* __restrict__ Ww,
                         half* __restrict__ WphH, half* __restrict__ WphL,
                         half* __restrict__ WgH,  half* __restrict__ WgL,
                         half* __restrict__ WthH,
                         half* __restrict__ WwH,  half* __restrict__ WwL)
{
    const int i = blockIdx.x * 256 + threadIdx.x;    // float4 chunk, 4*32768 total
    const int q = CI_ * C_ / 4;                       // 32768
    const int m = i / q, j = i % q;
    const float* src = (m == 0) ? Wph : (m == 1) ? Wg : (m == 2) ? Wth : Ww;
    half* dh = (m == 0) ? WphH : (m == 1) ? WgH : (m == 2) ? WthH : WwH;
    half* dl = (m == 0) ? WphL : (m == 1) ? WgL : (m == 2) ? nullptr : WwL;
    const float4 x = ((const float4*)src)[j];
    half2 h01 = __floats2half2_rn(x.x, x.y);
    half2 h23 = __floats2half2_rn(x.z, x.w);
    *(half2*)&dh[j * 4]     = h01;
    *(half2*)&dh[j * 4 + 2] = h23;
    if (dl) {
        float2 f01 = __half22float2(h01);
        float2 f23 = __half22float2(h23);
        *(half2*)&dl[j * 4]     = __floats2half2_rn(x.x - f01.x, x.y - f01.y);
        *(half2*)&dl[j * 4 + 2] = __floats2half2_rn(x.z - f23.x, x.w - f23.y);
    }
}

// ------------------------------------------------------------------------------
__global__ __launch_bounds__(256)
void zero_kernel(float* __restrict__ Zt)
{
    const int i = blockIdx.x * 256 + threadIdx.x;
    Zt[i] = 0.f;
    if (i < C_) { bn_sum[i] = 0.f; bn_sumsq[i] = 0.f; }
}

// ------------------------------------------------------------------------------
__global__ __launch_bounds__(256)
void bn_apply_kernel(const float* __restrict__ Wy,
                     const float* __restrict__ v,
                     const float* __restrict__ gamma,
                     const float* __restrict__ beta,
                     float* __restrict__ out)
{
    const long idx = (long)blockIdx.x * 256 + threadIdx.x;
    const long total4 = (long)B_ * C_ * N_ / 4;
    if (idx >= total4) return;
    const int c = (int)((idx * 4 / N_) % C_);
    const float inv = 1.f / (float)(B_ * N_);
    const float mean = bn_sum[c] * inv;
    const float var  = fmaxf(bn_sumsq[c] * inv - mean * mean, 0.f);
    const float rstd = rsqrtf(var + EPS_);
    const float sc = rstd * gamma[c];
    const float sh = beta[c] - mean * sc;
    const float4 w  = ((const float4*)Wy)[idx];
    const float4 vv = ((const float4*)v)[idx];
    float4 o;
    o.x = w.x * sc + sh + vv.x;
    o.y = w.y * sc + sh + vv.y;
    o.z = w.z * sc + sh + vv.z;
    o.w = w.w * sc + sh + vv.w;
    ((float4*)out)[idx] = o;
}

// ------------------------------------------------------------------------------
#define SYM(p, s) cudaGetSymbolAddress((void**)&p, s)

extern "C" void kernel_launch(void* const* d_in, const int* in_sizes, int n_in,
                              void* d_out, int out_size)
{
    const float* v     = (const float*)d_in[0];
    const float* Wg    = (const float*)d_in[1];
    const float* bg    = (const float*)d_in[2];
    const float* Wth   = (const float*)d_in[3];
    const float* bth   = (const float*)d_in[4];
    const float* Wph   = (const float*)d_in[5];
    const float* bph   = (const float*)d_in[6];
    const float* Ww    = (const float*)d_in[7];
    const float* bw    = (const float*)d_in[8];
    const float* gamma = (const float*)d_in[9];
    const float* beta  = (const float*)d_in[10];
    float* out = (float*)d_out;

    half *vTh, *vTl, *thh, *thl, *phh, *gh, *gl, *yh;
    half *WphH, *WphL, *WgH, *WgL, *WthH, *WwH, *WwL;
    float *Wy, *Zt;
    SYM(vTh, vT_h);  SYM(vTl, vT_l);
    SYM(thh, th_h);  SYM(thl, th_l);
    SYM(phh, ph_h);
    SYM(gh,  g_h);   SYM(gl,  g_l);
    SYM(yh,  y_h);
    SYM(WphH, Wph_h); SYM(WphL, Wph_l);
    SYM(WgH,  Wg_h);  SYM(WgL,  Wg_l);
    SYM(WthH, Wth_h);
    SYM(WwH,  Ww_h);  SYM(WwL,  Ww_l);
    SYM(Wy,  Wy_buf);
    SYM(Zt,  Zt_buf);

    cudaFuncSetAttribute(gemm_h2<2, true,  false, false>, cudaFuncAttributeMaxDynamicSharedMemorySize, SMEM_GEMM_BYTES);
    cudaFuncSetAttribute(gemm_h2<1, true,  false, false>, cudaFuncAttributeMaxDynamicSharedMemorySize, SMEM_GEMM_BYTES);
    cudaFuncSetAttribute(gemm_h2<0, true,  false, true >, cudaFuncAttributeMaxDynamicSharedMemorySize, SMEM_GEMM_BYTES);
    cudaFuncSetAttribute(gemm_h2<2, false, false, false>, cudaFuncAttributeMaxDynamicSharedMemorySize, SMEM_GEMM_BYTES);
    cudaFuncSetAttribute(gemm_h2<0, true,  true,  false>, cudaFuncAttributeMaxDynamicSharedMemorySize, SMEM_GEMM_BYTES);

    const long sVT = (long)N_ * C_;    // vT batch stride (halves)
    const long sNC = (long)N_ * CI_;   // [N,Ci]
    const long sCN = (long)CI_ * N_;   // [Ci,N]
    const long sC  = (long)C_ * N_;    // [C,N] fp32
    const long sZ  = (long)CI_ * CI_;

    // 0) zero Zt + BN; split weights; transpose+split v
    zero_kernel<<<(B_ * CI_ * CI_) / 256, 256>>>(Zt);
    prep_weights_kernel<<<(4 * CI_ * C_ / 4) / 256, 256>>>(
        Wph, Wg, Wth, Ww, WphH, WphL, WgH, WgL, WthH, WwH, WwL);
    transpose_split_kernel<<<dim3(N_ / 32, C_ / 32, B_), dim3(32, 8)>>>(v, vTh, vTl);

    // 1) ph[ci,n] = Wph . vT^T + bph   (hi-only out; biasM)
    gemm_h2<2, true, false, false><<<dim3(N_ / 64, CI_ / 128, B_), 256, SMEM_GEMM_BYTES>>>(
        WphH, WphL, vTh, nullptr, nullptr, phh, nullptr, bph, nullptr,
        CI_, N_, C_, C_, C_, 1.f, 1, 0, 0, sVT, 0, sCN, 0);
    // 2) g[ci,n] = Wg . vT^T + bg      (hi+lo out)
    gemm_h2<1, true, false, false><<<dim3(N_ / 64, CI_ / 128, B_), 256, SMEM_GEMM_BYTES>>>(
        WgH, WgL, vTh, nullptr, nullptr, gh, gl, bg, nullptr,
        CI_, N_, C_, C_, C_, 1.f, 1, 0, 0, sVT, 0, sCN, 0);
    // 3) Zt[cg,cth] += (ZSCALE/N) g . ph^T   (split-K atomic fp32)
    gemm_h2<0, true, false, true><<<dim3(CI_ / 64, CI_ / 128, B_ * SLICES), 256, SMEM_GEMM_BYTES>>>(
        gh, gl, phh, nullptr, Zt, nullptr, nullptr, nullptr, nullptr,
        CI_, CI_, N_ / SLICES, N_, N_, ZSCALE / (float)N_,
        SLICES, sCN, N_ / SLICES, sCN, N_ / SLICES, sZ, 0);
    // 4) th[n,cth] = vT . Wth^T + bth   (hi+lo out; biasN)
    gemm_h2<1, true, false, false><<<dim3(CI_ / 64, N_ / 128, B_), 256, SMEM_GEMM_BYTES>>>(
        vTh, vTl, WthH, nullptr, nullptr, thh, thl, nullptr, bth,
        N_, CI_, C_, C_, C_, 1.f, 1, sVT, 0, 0, 0, sNC, 0);
    // 5) y[n,cg] = (1/ZSCALE) th . Zt^T   (B fp32; hi-only out)
    gemm_h2<2, false, false, false><<<dim3(CI_ / 64, N_ / 128, B_), 256, SMEM_GEMM_BYTES>>>(
        thh, thl, nullptr, Zt, nullptr, yh, nullptr, nullptr, nullptr,
        N_, CI_, CI_, CI_, CI_, 1.f / ZSCALE, 1, sNC, 0, sZ, 0, sNC, 0);
    // 6) Wy[c,n] = Ww . y^T + bw        (fp32 out; BN stats in epilogue)
    gemm_h2<0, true, true, false><<<dim3(N_ / 64, C_ / 128, B_), 256, SMEM_GEMM_BYTES>>>(
        WwH, WwL, yh, nullptr, Wy, nullptr, nullptr, bw, nullptr,
        C_, N_, CI_, CI_, CI_, 1.f, 1, 0, 0, sNC, 0, sC, 0);

    // 7) BN apply + affine + residual
    const long total4 = (long)B_ * C_ * N_ / 4;
    bn_apply_kernel<<<(int)((total4 + 255) / 256), 256>>>(Wy, v, gamma, beta, out);
}

// round 13
// speedup vs baseline: 1.2573x; 1.2573x over previous
#include <cuda_runtime.h>
#include <cuda_fp16.h>
#include <cstdint>

#define B_  4
#define C_  512
#define CI_ 256
#define N_  4096
#define EPS_ 1e-5f
#define ZSCALE 64.0f
#define SLICES 16

// ------------------------- device scratch (no allocs) -------------------------
__device__ float vT_buf[B_ * N_ * C_];                 // 32 MB [B,N,C]
__device__ float th_buf[B_ * N_ * CI_];                // 16 MB [B,N,Ci]
__device__ float ph_buf[B_ * CI_ * N_];                // 16 MB [B,Ci,N]
__device__ float g_buf [B_ * CI_ * N_];                // 16 MB [B,Ci,N]
__device__ float y_buf [B_ * N_ * CI_];                // 16 MB [B,N,Ci]
__device__ float Wy_buf[B_ * C_ * N_];                 // 32 MB [B,C,N]
__device__ float Zt_buf[B_ * CI_ * CI_];               //  1 MB [B,cg,cth]
__device__ float bn_sum[C_];
__device__ float bn_sumsq[C_];

// ------------------------------- GEMM config ----------------------------------
// CTA tile 128(M) x 64(N) x 32(K), 256 threads (8 warps, 4x2, 32x32 each).
// A_X1=1: A hi-plane only (single MMA pass). A_X1=0: A hi+lo (two passes).
#define PITCH 40                         // halves per smem row (80B), conflict-free
#define ROWB  (PITCH * 2)                // 80 bytes per row
#define A_TILE_B 10240                   // 128 rows * 80B (per plane)
#define B_TILE_B 5120                    // 64 rows * 80B (hi plane only)
#define A_TILE_H (A_TILE_B / 2)
#define OFF_BH   (2 * A_TILE_B)          // 20480: B-hi plane offset
#define BUF_BYTES (2 * A_TILE_B + B_TILE_B)        // 25600
#define SMEM_GEMM_BYTES (2 * BUF_BYTES + 1024)     // 52224

__device__ __forceinline__ uint32_t smem_u32(const void* p) {
    uint32_t a;
    asm("{ .reg .u64 t; cvta.to.shared.u64 t, %1; cvt.u32.u64 %0, t; }" : "=r"(a) : "l"(p));
    return a;
}
__device__ __forceinline__ void ldm_x4(uint32_t* r, uint32_t addr) {
    asm volatile("ldmatrix.sync.aligned.m8n8.x4.shared.b16 {%0,%1,%2,%3}, [%4];"
                 : "=r"(r[0]), "=r"(r[1]), "=r"(r[2]), "=r"(r[3]) : "r"(addr));
}
__device__ __forceinline__ void mma16816(float* c, const uint32_t* a, const uint32_t* b) {
    asm volatile(
        "mma.sync.aligned.m16n8k16.row.col.f32.f16.f16.f32 "
        "{%0,%1,%2,%3}, {%4,%5,%6,%7}, {%8,%9}, {%0,%1,%2,%3};"
        : "+f"(c[0]), "+f"(c[1]), "+f"(c[2]), "+f"(c[3])
        : "r"(a[0]), "r"(a[1]), "r"(a[2]), "r"(a[3]), "r"(b[0]), "r"(b[1]));
}

// split fp32x4 -> hi/lo fp16 pairs (lo at +A_TILE_H halves)
__device__ __forceinline__ void split_store(half* base, int idx, float4 x) {
    half2 h01 = __floats2half2_rn(x.x, x.y);
    half2 h23 = __floats2half2_rn(x.z, x.w);
    float2 f01 = __half22float2(h01);
    float2 f23 = __half22float2(h23);
    half2 l01 = __floats2half2_rn(x.x - f01.x, x.y - f01.y);
    half2 l23 = __floats2half2_rn(x.z - f23.x, x.w - f23.y);
    *(half2*)&base[idx]     = h01;
    *(half2*)&base[idx + 2] = h23;
    *(half2*)&base[A_TILE_H + idx]     = l01;
    *(half2*)&base[A_TILE_H + idx + 2] = l23;
}
// hi plane only
__device__ __forceinline__ void store_hi(half* base, int idx, float4 x) {
    *(half2*)&base[idx]     = __floats2half2_rn(x.x, x.y);
    *(half2*)&base[idx + 2] = __floats2half2_rn(x.z, x.w);
}

// ------------------------------------------------------------------------------
// D[M,Nt] = alpha * A[M,K] @ B[Nt,K]^T + biasM[row] + biasN[col]
// A, B fp32 row-major, strides ldA/ldB (K contiguous). 128x64x32 tiles, 256 thr.
// grid = (Nt/64, M/128, nBatch*nSlices); per-z: X += b*sbX + s*slX.
// A_X1: single-pass (A hi only). Else fp16x2 (hh + lh), fp32 accumulate.
// BN_ACC: accumulate per-row sum/sumsq into bn_sum/bn_sumsq (atomics).
// ATOMIC_OUT: atomicAdd into D (split-K reduction); biases must be null.
// ------------------------------------------------------------------------------
template <bool A_X1, bool BN_ACC, bool ATOMIC_OUT>
__global__ __launch_bounds__(256, 2)
void gemm_fp16h(const float* __restrict__ A, const float* __restrict__ Bm,
                float* __restrict__ D,
                const float* __restrict__ biasM, const float* __restrict__ biasN,
                int M, int Nt, int K, int ldA, int ldB, float alpha,
                int nSlices,
                long sbA, long slA, long sbB, long slB, long sbD, long slD)
{
    extern __shared__ char smem[];
    half*  sh  = (half*)smem;
    float* sBM = (float*)(smem + 2 * BUF_BYTES);
    float* sBN = sBM + 128;
    const uint32_t sbu = smem_u32(sh);

    const int tid = threadIdx.x;
    const int bx = blockIdx.x, by = blockIdx.y, bz = blockIdx.z;
    const int bb = bz / nSlices;
    const int ss = bz % nSlices;
    A  += bb * sbA + ss * slA + (long)(by * 128) * ldA;
    Bm += bb * sbB + ss * slB + (long)(bx * 64) * ldB;
    D  += bb * sbD + ss * slD;

    if (tid < 128) sBM[tid] = biasM ? biasM[by * 128 + tid] : 0.f;
    if (tid < 64)  sBN[tid] = biasN ? biasN[bx * 64 + tid] : 0.f;

    const int sf = tid & 7;       // k-chunk (4 floats)
    const int sr = tid >> 3;      // 0..31 (row base)
    const int nIter = K / 32;

    const float* pA[4];
    const float* pB[2];
#pragma unroll
    for (int i = 0; i < 4; ++i)
        pA[i] = A + (long)(sr + 32 * i) * ldA + sf * 4;
#pragma unroll
    for (int i = 0; i < 2; ++i)
        pB[i] = Bm + (long)(sr + 32 * i) * ldB + sf * 4;

    float4 ra[4], rb[2];
#pragma unroll
    for (int i = 0; i < 4; ++i) { ra[i] = *(const float4*)pA[i]; pA[i] += 32; }
#pragma unroll
    for (int i = 0; i < 2; ++i) { rb[i] = *(const float4*)pB[i]; pB[i] += 32; }
    {
        half* Ab = sh;
        half* Bb = sh + OFF_BH / 2;
#pragma unroll
        for (int i = 0; i < 4; ++i) {
            const int idx = (sr + 32 * i) * PITCH + sf * 4;
            if (A_X1) store_hi(Ab, idx, ra[i]);
            else      split_store(Ab, idx, ra[i]);
        }
#pragma unroll
        for (int i = 0; i < 2; ++i)
            store_hi(Bb, (sr + 32 * i) * PITCH + sf * 4, rb[i]);
    }
    __syncthreads();

    float acc[2][4][4];
#pragma unroll
    for (int mi = 0; mi < 2; ++mi)
#pragma unroll
        for (int ni = 0; ni < 4; ++ni)
#pragma unroll
            for (int q = 0; q < 4; ++q) acc[mi][ni][q] = 0.f;

    const int wid = tid >> 5, lid = tid & 31;
    const int wm = (wid >> 1) * 32;   // warp m offset: 0/32/64/96
    const int wn = (wid & 1) * 32;    // warp n offset: 0/32
    const int g = lid >> 2;
    const int t = lid & 3;

    const uint32_t laneA = (uint32_t)((lid & 15) * ROWB + (lid >> 4) * 16);
    const uint32_t laneB = (uint32_t)((((lid >> 4) * 8) + (lid & 7)) * ROWB
                                      + ((lid >> 3) & 1) * 16);
    const uint32_t aWarp = sbu + (uint32_t)(wm * ROWB) + laneA;
    const uint32_t bWarp = sbu + OFF_BH + (uint32_t)(wn * ROWB) + laneB;

    for (int it = 0; it < nIter; ++it) {
        const int buf = it & 1;
        const bool hasNext = (it + 1 < nIter);
        if (hasNext) {
#pragma unroll
            for (int i = 0; i < 4; ++i) { ra[i] = *(const float4*)pA[i]; pA[i] += 32; }
#pragma unroll
            for (int i = 0; i < 2; ++i) { rb[i] = *(const float4*)pB[i]; pB[i] += 32; }
        }

        const uint32_t bo = (uint32_t)(buf * BUF_BYTES);
#pragma unroll
        for (int kk = 0; kk < 2; ++kk) {
            const uint32_t ko = (uint32_t)(kk * 32);
            uint32_t ah[2][4], al[2][4];
#pragma unroll
            for (int mi = 0; mi < 2; ++mi) {
                const uint32_t addr = aWarp + bo + (uint32_t)(mi * 16 * ROWB) + ko;
                ldm_x4(ah[mi], addr);
                if (!A_X1) ldm_x4(al[mi], addr + A_TILE_B);
            }
            uint32_t bh[2][4];
#pragma unroll
            for (int nb = 0; nb < 2; ++nb) {
                const uint32_t addr = bWarp + bo + (uint32_t)(nb * 16 * ROWB) + ko;
                ldm_x4(bh[nb], addr);
            }
#pragma unroll
            for (int mi = 0; mi < 2; ++mi)
#pragma unroll
                for (int ni = 0; ni < 4; ++ni)
                    mma16816(acc[mi][ni], ah[mi], &bh[ni >> 1][(ni & 1) * 2]);
            if (!A_X1) {
#pragma unroll
                for (int mi = 0; mi < 2; ++mi)
#pragma unroll
                    for (int ni = 0; ni < 4; ++ni)
                        mma16816(acc[mi][ni], al[mi], &bh[ni >> 1][(ni & 1) * 2]);
            }
        }

        if (hasNext) {
            half* Ab = sh + (buf ^ 1) * (BUF_BYTES / 2);
            half* Bb = Ab + OFF_BH / 2;
#pragma unroll
            for (int i = 0; i < 4; ++i) {
                const int idx = (sr + 32 * i) * PITCH + sf * 4;
                if (A_X1) store_hi(Ab, idx, ra[i]);
                else      split_store(Ab, idx, ra[i]);
            }
#pragma unroll
            for (int i = 0; i < 2; ++i)
                store_hi(Bb, (sr + 32 * i) * PITCH + sf * 4, rb[i]);
        }
        __syncthreads();
    }

    // ---------------- epilogue ----------------
#pragma unroll
    for (int mi = 0; mi < 2; ++mi) {
        const int rowLoc = wm + mi * 16 + g;
        const int chan0 = by * 128 + rowLoc;
        const float bm0 = sBM[rowLoc], bm1 = sBM[rowLoc + 8];
        const long gr0 = (long)chan0 * Nt + bx * 64;
        const long gr1 = gr0 + 8L * Nt;
        float s0 = 0.f, q0 = 0.f, s1 = 0.f, q1 = 0.f;
#pragma unroll
        for (int ni = 0; ni < 4; ++ni) {
            const int col = wn + ni * 8 + t * 2;
            const float bn0 = sBN[col], bn1 = sBN[col + 1];
            float2 o0, o1;
            o0.x = alpha * acc[mi][ni][0] + bm0 + bn0;
            o0.y = alpha * acc[mi][ni][1] + bm0 + bn1;
            o1.x = alpha * acc[mi][ni][2] + bm1 + bn0;
            o1.y = alpha * acc[mi][ni][3] + bm1 + bn1;
            if (ATOMIC_OUT) {
                atomicAdd(&D[gr0 + col],     o0.x);
                atomicAdd(&D[gr0 + col + 1], o0.y);
                atomicAdd(&D[gr1 + col],     o1.x);
                atomicAdd(&D[gr1 + col + 1], o1.y);
            } else {
                *(float2*)&D[gr0 + col] = o0;
                *(float2*)&D[gr1 + col] = o1;
            }
            if (BN_ACC) {
                s0 += o0.x + o0.y;  q0 += o0.x * o0.x + o0.y * o0.y;
                s1 += o1.x + o1.y;  q1 += o1.x * o1.x + o1.y * o1.y;
            }
        }
        if (BN_ACC) {
#pragma unroll
            for (int o = 1; o < 4; o <<= 1) {
                s0 += __shfl_xor_sync(0xFFFFFFFF, s0, o);
                q0 += __shfl_xor_sync(0xFFFFFFFF, q0, o);
                s1 += __shfl_xor_sync(0xFFFFFFFF, s1, o);
                q1 += __shfl_xor_sync(0xFFFFFFFF, q1, o);
            }
            if (t == 0) {
                atomicAdd(&bn_sum[chan0],       s0);
                atomicAdd(&bn_sumsq[chan0],     q0);
                atomicAdd(&bn_sum[chan0 + 8],   s1);
                atomicAdd(&bn_sumsq[chan0 + 8], q1);
            }
        }
    }
}

// ------------------------------------------------------------------------------
// v [B,C,N] -> vT [B,N,C]
__global__ __launch_bounds__(256)
void transpose_kernel(const float* __restrict__ v, float* __restrict__ o)
{
    __shared__ float t[32][33];
    const int b = blockIdx.z;
    const int n0 = blockIdx.x * 32, c0 = blockIdx.y * 32;
    const int tx = threadIdx.x, ty = threadIdx.y;   // 32 x 8
#pragma unroll
    for (int i = 0; i < 4; ++i)
        t[ty + 8 * i][tx] = v[((long)b * C_ + c0 + ty + 8 * i) * N_ + n0 + tx];
    __syncthreads();
#pragma unroll
    for (int i = 0; i < 4; ++i)
        o[((long)b * N_ + n0 + ty + 8 * i) * C_ + c0 + tx] = t[tx][ty + 8 * i];
}

// ------------------------------------------------------------------------------
__global__ __launch_bounds__(256)
void zero_kernel(float* __restrict__ Zt)
{
    const int i = blockIdx.x * 256 + threadIdx.x;
    Zt[i] = 0.f;
    if (i < C_) { bn_sum[i] = 0.f; bn_sumsq[i] = 0.f; }
}

// ------------------------------------------------------------------------------
__global__ __launch_bounds__(256)
void bn_apply_kernel(const float* __restrict__ Wy,
                     const float* __restrict__ v,
                     const float* __restrict__ gamma,
                     const float* __restrict__ beta,
                     float* __restrict__ out)
{
    const long idx = (long)blockIdx.x * 256 + threadIdx.x;
    const long total4 = (long)B_ * C_ * N_ / 4;
    if (idx >= total4) return;
    const int c = (int)((idx * 4 / N_) % C_);
    const float inv = 1.f / (float)(B_ * N_);
    const float mean = bn_sum[c] * inv;
    const float var  = fmaxf(bn_sumsq[c] * inv - mean * mean, 0.f);
    const float rstd = rsqrtf(var + EPS_);
    const float sc = rstd * gamma[c];
    const float sh = beta[c] - mean * sc;
    const float4 w  = ((const float4*)Wy)[idx];
    const float4 vv = ((const float4*)v)[idx];
    float4 o;
    o.x = w.x * sc + sh + vv.x;
    o.y = w.y * sc + sh + vv.y;
    o.z = w.z * sc + sh + vv.z;
    o.w = w.w * sc + sh + vv.w;
    ((float4*)out)[idx] = o;
}

// ------------------------------------------------------------------------------
#define SYM(p, s) cudaGetSymbolAddress((void**)&p, s)

extern "C" void kernel_launch(void* const* d_in, const int* in_sizes, int n_in,
                              void* d_out, int out_size)
{
    const float* v     = (const float*)d_in[0];
    const float* Wg    = (const float*)d_in[1];
    const float* bg    = (const float*)d_in[2];
    const float* Wth   = (const float*)d_in[3];
    const float* bth   = (const float*)d_in[4];
    const float* Wph   = (const float*)d_in[5];
    const float* bph   = (const float*)d_in[6];
    const float* Ww    = (const float*)d_in[7];
    const float* bw    = (const float*)d_in[8];
    const float* gamma = (const float*)d_in[9];
    const float* beta  = (const float*)d_in[10];
    float* out = (float*)d_out;

    float *vT, *th, *ph, *g, *y, *Wy, *Zt;
    SYM(vT, vT_buf);
    SYM(th, th_buf);
    SYM(ph, ph_buf);
    SYM(g,  g_buf);
    SYM(y,  y_buf);
    SYM(Wy, Wy_buf);
    SYM(Zt, Zt_buf);

    cudaFuncSetAttribute(gemm_fp16h<true,  false, false>, cudaFuncAttributeMaxDynamicSharedMemorySize, SMEM_GEMM_BYTES);
    cudaFuncSetAttribute(gemm_fp16h<false, false, true >, cudaFuncAttributeMaxDynamicSharedMemorySize, SMEM_GEMM_BYTES);
    cudaFuncSetAttribute(gemm_fp16h<false, false, false>, cudaFuncAttributeMaxDynamicSharedMemorySize, SMEM_GEMM_BYTES);
    cudaFuncSetAttribute(gemm_fp16h<false, true,  false>, cudaFuncAttributeMaxDynamicSharedMemorySize, SMEM_GEMM_BYTES);

    const long sVT = (long)N_ * C_;    // vT batch stride
    const long sNC = (long)N_ * CI_;   // [N,Ci]
    const long sCN = (long)CI_ * N_;   // [Ci,N]
    const long sC  = (long)C_ * N_;    // [C,N]
    const long sZ  = (long)CI_ * CI_;  // 65536

    // 0) zero Zt + BN accumulators; transpose v -> vT
    zero_kernel<<<(B_ * CI_ * CI_) / 256, 256>>>(Zt);
    transpose_kernel<<<dim3(N_ / 32, C_ / 32, B_), dim3(32, 8)>>>(v, vT);

    // 1) ph[ci,n] = Wph[ci,:].vT[n,:] + bph[ci]     (x1; biasM)
    gemm_fp16h<true, false, false><<<dim3(N_ / 64, CI_ / 128, B_), 256, SMEM_GEMM_BYTES>>>(
        Wph, vT, ph, bph, nullptr, CI_, N_, C_, C_, C_, 1.f,
        1, 0, 0, sVT, 0, sCN, 0);
    // 2) g[ci,n] = Wg[ci,:].vT[n,:] + bg[ci]        (x1)
    gemm_fp16h<true, false, false><<<dim3(N_ / 64, CI_ / 128, B_), 256, SMEM_GEMM_BYTES>>>(
        Wg, vT, g, bg, nullptr, CI_, N_, C_, C_, C_, 1.f,
        1, 0, 0, sVT, 0, sCN, 0);
    // 3) Zt[b][cg,cth] += (ZSCALE/N) g . ph^T       (x2; split-K atomic)
    gemm_fp16h<false, false, true><<<dim3(CI_ / 64, CI_ / 128, B_ * SLICES), 256, SMEM_GEMM_BYTES>>>(
        g, ph, Zt, nullptr, nullptr, CI_, CI_, N_ / SLICES, N_, N_, ZSCALE / (float)N_,
        SLICES, sCN, N_ / SLICES, sCN, N_ / SLICES, sZ, 0);
    // 4) th[n,cth] = vT[n,:].Wth[cth,:] + bth       (x1; biasN)
    gemm_fp16h<true, false, false><<<dim3(CI_ / 64, N_ / 128, B_), 256, SMEM_GEMM_BYTES>>>(
        vT, Wth, th, nullptr, bth, N_, CI_, C_, C_, C_, 1.f,
        1, sVT, 0, 0, 0, sNC, 0);
    // 5) y[n,cg] = (1/ZSCALE) th . Zt^T             (x2)
    gemm_fp16h<false, false, false><<<dim3(CI_ / 64, N_ / 128, B_), 256, SMEM_GEMM_BYTES>>>(
        th, Zt, y, nullptr, nullptr, N_, CI_, CI_, CI_, CI_, 1.f / ZSCALE,
        1, sNC, 0, sZ, 0, sNC, 0);
    // 6) Wy[c,n] = Ww . y^T + bw                    (x2; biasM; BN stats)
    gemm_fp16h<false, true, false><<<dim3(N_ / 64, C_ / 128, B_), 256, SMEM_GEMM_BYTES>>>(
        Ww, y, Wy, bw, nullptr, C_, N_, CI_, CI_, CI_, 1.f,
        1, 0, 0, sNC, 0, sC, 0);

    // 7) BN apply + affine + residual
    const long total4 = (long)B_ * C_ * N_ / 4;
    bn_apply_kernel<<<(int)((total4 + 255) / 256), 256>>>(Wy, v, gamma, beta, out);
}

// round 14
// speedup vs baseline: 1.2688x; 1.0091x over previous
#include <cuda_runtime.h>
#include <cuda_fp16.h>
#include <cstdint>

#define B_  4
#define C_  512
#define CI_ 256
#define N_  4096
#define EPS_ 1e-5f
#define ZSCALE 64.0f
#define SLICES 16

// ------------------------- device scratch (no allocs) -------------------------
__device__ half  vT_h [B_ * N_ * C_];                  //  16 MB [B,N,C] fp16 hi
__device__ half  WphH [CI_ * C_];
__device__ half  WgH  [CI_ * C_];
__device__ half  WthH [CI_ * C_];
__device__ float th_buf[B_ * N_ * CI_];                // 16 MB [B,N,Ci]
__device__ float ph_buf[B_ * CI_ * N_];                // 16 MB [B,Ci,N]
__device__ float g_buf [B_ * CI_ * N_];                // 16 MB [B,Ci,N]
__device__ float y_buf [B_ * N_ * CI_];                // 16 MB [B,N,Ci]
__device__ float Wy_buf[B_ * C_ * N_];                 // 32 MB [B,C,N]
__device__ float Zt_buf[B_ * CI_ * CI_];               //  1 MB [B,cg,cth]
__device__ float bn_sum[C_];
__device__ float bn_sumsq[C_];

// ------------------------------- GEMM config ----------------------------------
#define PITCH 40                         // halves per smem row (80B), conflict-free
#define ROWB  (PITCH * 2)                // 80 bytes per row
#define A_TILE_B 10240                   // 128 rows * 80B (per plane)
#define B_TILE_B 5120                    // 64 rows * 80B
#define A_TILE_H (A_TILE_B / 2)
#define OFF_BH   (2 * A_TILE_B)          // fp32 kernel: B-hi offset after A hi+lo
#define BUF_BYTES (2 * A_TILE_B + B_TILE_B)        // 25600 (fp32 x2 kernel)
#define SMEM_GEMM_BYTES (2 * BUF_BYTES + 1024)     // 52224
// h1 kernel: A hi + B hi only
#define OFF_BH1   A_TILE_B               // 10240
#define BUF1_BYTES (A_TILE_B + B_TILE_B)           // 15360
#define SMEM_H1_BYTES (2 * BUF1_BYTES + 1024)      // 31744

__device__ __forceinline__ uint32_t smem_u32(const void* p) {
    uint32_t a;
    asm("{ .reg .u64 t; cvta.to.shared.u64 t, %1; cvt.u32.u64 %0, t; }" : "=r"(a) : "l"(p));
    return a;
}
__device__ __forceinline__ void ldm_x4(uint32_t* r, uint32_t addr) {
    asm volatile("ldmatrix.sync.aligned.m8n8.x4.shared.b16 {%0,%1,%2,%3}, [%4];"
                 : "=r"(r[0]), "=r"(r[1]), "=r"(r[2]), "=r"(r[3]) : "r"(addr));
}
__device__ __forceinline__ void mma16816(float* c, const uint32_t* a, const uint32_t* b) {
    asm volatile(
        "mma.sync.aligned.m16n8k16.row.col.f32.f16.f16.f32 "
        "{%0,%1,%2,%3}, {%4,%5,%6,%7}, {%8,%9}, {%0,%1,%2,%3};"
        : "+f"(c[0]), "+f"(c[1]), "+f"(c[2]), "+f"(c[3])
        : "r"(a[0]), "r"(a[1]), "r"(a[2]), "r"(a[3]), "r"(b[0]), "r"(b[1]));
}

// split fp32x4 -> hi/lo fp16 pairs (lo at +A_TILE_H halves)
__device__ __forceinline__ void split_store(half* base, int idx, float4 x) {
    half2 h01 = __floats2half2_rn(x.x, x.y);
    half2 h23 = __floats2half2_rn(x.z, x.w);
    float2 f01 = __half22float2(h01);
    float2 f23 = __half22float2(h23);
    half2 l01 = __floats2half2_rn(x.x - f01.x, x.y - f01.y);
    half2 l23 = __floats2half2_rn(x.z - f23.x, x.w - f23.y);
    *(half2*)&base[idx]     = h01;
    *(half2*)&base[idx + 2] = h23;
    *(half2*)&base[A_TILE_H + idx]     = l01;
    *(half2*)&base[A_TILE_H + idx + 2] = l23;
}
__device__ __forceinline__ void store_hi(half* base, int idx, float4 x) {
    *(half2*)&base[idx]     = __floats2half2_rn(x.x, x.y);
    *(half2*)&base[idx + 2] = __floats2half2_rn(x.z, x.w);
}

// ==============================================================================
// gemm_h1: D[M,Nt] = A[M,K](fp16) @ B[Nt,K](fp16)^T + biasM + biasN   (single pass)
// A, B pre-converted fp16-hi, K-contiguous, strides in halves.
// 128x64x32 tiles, 256 threads, 2 CTAs/SM. grid = (Nt/64, M/128, nBatch).
// ==============================================================================
__global__ __launch_bounds__(256, 2)
void gemm_h1(const half* __restrict__ A, const half* __restrict__ Bm,
             float* __restrict__ D,
             const float* __restrict__ biasM, const float* __restrict__ biasN,
             int M, int Nt, int K, int ldA, int ldB,
             long sbA, long sbB, long sbD)
{
    extern __shared__ char smem[];
    half*  sh  = (half*)smem;
    float* sBM = (float*)(smem + 2 * BUF1_BYTES);
    float* sBN = sBM + 128;
    const uint32_t sbu = smem_u32(sh);

    const int tid = threadIdx.x;
    const int bx = blockIdx.x, by = blockIdx.y, bz = blockIdx.z;
    A  += bz * sbA + (long)(by * 128) * ldA;
    Bm += bz * sbB + (long)(bx * 64) * ldB;
    D  += bz * sbD;

    if (tid < 128) sBM[tid] = biasM ? biasM[by * 128 + tid] : 0.f;
    if (tid < 64)  sBN[tid] = biasN ? biasN[bx * 64 + tid] : 0.f;

    const int sf = tid & 7;       // 4-half chunk (8B)
    const int sr = tid >> 3;      // 0..31 row base
    const int nIter = K / 32;

    const half* pA[4];
    const half* pB[2];
#pragma unroll
    for (int i = 0; i < 4; ++i)
        pA[i] = A + (long)(sr + 32 * i) * ldA + sf * 4;
#pragma unroll
    for (int i = 0; i < 2; ++i)
        pB[i] = Bm + (long)(sr + 32 * i) * ldB + sf * 4;

    uint2 ra[4], rb[2];
#pragma unroll
    for (int i = 0; i < 4; ++i) { ra[i] = *(const uint2*)pA[i]; pA[i] += 32; }
#pragma unroll
    for (int i = 0; i < 2; ++i) { rb[i] = *(const uint2*)pB[i]; pB[i] += 32; }
    {
        half* Ab = sh;
        half* Bb = sh + OFF_BH1 / 2;
#pragma unroll
        for (int i = 0; i < 4; ++i)
            *(uint2*)&Ab[(sr + 32 * i) * PITCH + sf * 4] = ra[i];
#pragma unroll
        for (int i = 0; i < 2; ++i)
            *(uint2*)&Bb[(sr + 32 * i) * PITCH + sf * 4] = rb[i];
    }
    __syncthreads();

    float acc[2][4][4];
#pragma unroll
    for (int mi = 0; mi < 2; ++mi)
#pragma unroll
        for (int ni = 0; ni < 4; ++ni)
#pragma unroll
            for (int q = 0; q < 4; ++q) acc[mi][ni][q] = 0.f;

    const int wid = tid >> 5, lid = tid & 31;
    const int wm = (wid >> 1) * 32;
    const int wn = (wid & 1) * 32;
    const int g = lid >> 2;
    const int t = lid & 3;

    const uint32_t laneA = (uint32_t)((lid & 15) * ROWB + (lid >> 4) * 16);
    const uint32_t laneB = (uint32_t)((((lid >> 4) * 8) + (lid & 7)) * ROWB
                                      + ((lid >> 3) & 1) * 16);
    const uint32_t aWarp = sbu + (uint32_t)(wm * ROWB) + laneA;
    const uint32_t bWarp = sbu + OFF_BH1 + (uint32_t)(wn * ROWB) + laneB;

    for (int it = 0; it < nIter; ++it) {
        const int buf = it & 1;
        const bool hasNext = (it + 1 < nIter);
        if (hasNext) {
#pragma unroll
            for (int i = 0; i < 4; ++i) { ra[i] = *(const uint2*)pA[i]; pA[i] += 32; }
#pragma unroll
            for (int i = 0; i < 2; ++i) { rb[i] = *(const uint2*)pB[i]; pB[i] += 32; }
        }

        const uint32_t bo = (uint32_t)(buf * BUF1_BYTES);
#pragma unroll
        for (int kk = 0; kk < 2; ++kk) {
            const uint32_t ko = (uint32_t)(kk * 32);
            uint32_t ah[2][4];
#pragma unroll
            for (int mi = 0; mi < 2; ++mi)
                ldm_x4(ah[mi], aWarp + bo + (uint32_t)(mi * 16 * ROWB) + ko);
            uint32_t bh[2][4];
#pragma unroll
            for (int nb = 0; nb < 2; ++nb)
                ldm_x4(bh[nb], bWarp + bo + (uint32_t)(nb * 16 * ROWB) + ko);
#pragma unroll
            for (int mi = 0; mi < 2; ++mi)
#pragma unroll
                for (int ni = 0; ni < 4; ++ni)
                    mma16816(acc[mi][ni], ah[mi], &bh[ni >> 1][(ni & 1) * 2]);
        }

        if (hasNext) {
            half* Ab = sh + (buf ^ 1) * (BUF1_BYTES / 2);
            half* Bb = Ab + OFF_BH1 / 2;
#pragma unroll
            for (int i = 0; i < 4; ++i)
                *(uint2*)&Ab[(sr + 32 * i) * PITCH + sf * 4] = ra[i];
#pragma unroll
            for (int i = 0; i < 2; ++i)
                *(uint2*)&Bb[(sr + 32 * i) * PITCH + sf * 4] = rb[i];
        }
        __syncthreads();
    }

    // epilogue (fp32 out + biases)
#pragma unroll
    for (int mi = 0; mi < 2; ++mi) {
        const int rowLoc = wm + mi * 16 + g;
        const float bm0 = sBM[rowLoc], bm1 = sBM[rowLoc + 8];
        const long gr0 = (long)(by * 128 + rowLoc) * Nt + bx * 64;
        const long gr1 = gr0 + 8L * Nt;
#pragma unroll
        for (int ni = 0; ni < 4; ++ni) {
            const int col = wn + ni * 8 + t * 2;
            const float bn0 = sBN[col], bn1 = sBN[col + 1];
            float2 o0, o1;
            o0.x = acc[mi][ni][0] + bm0 + bn0;
            o0.y = acc[mi][ni][1] + bm0 + bn1;
            o1.x = acc[mi][ni][2] + bm1 + bn0;
            o1.y = acc[mi][ni][3] + bm1 + bn1;
            *(float2*)&D[gr0 + col] = o0;
            *(float2*)&D[gr1 + col] = o1;
        }
    }
}

// ==============================================================================
// gemm_fp16h: fp32-input x2 kernel (unchanged from R13, A_X1=false paths only)
// ==============================================================================
template <bool BN_ACC, bool ATOMIC_OUT>
__global__ __launch_bounds__(256, 2)
void gemm_fp16h(const float* __restrict__ A, const float* __restrict__ Bm,
                float* __restrict__ D,
                const float* __restrict__ biasM, const float* __restrict__ biasN,
                int M, int Nt, int K, int ldA, int ldB, float alpha,
                int nSlices,
                long sbA, long slA, long sbB, long slB, long sbD, long slD)
{
    extern __shared__ char smem[];
    half*  sh  = (half*)smem;
    float* sBM = (float*)(smem + 2 * BUF_BYTES);
    float* sBN = sBM + 128;
    const uint32_t sbu = smem_u32(sh);

    const int tid = threadIdx.x;
    const int bx = blockIdx.x, by = blockIdx.y, bz = blockIdx.z;
    const int bb = bz / nSlices;
    const int ss = bz % nSlices;
    A  += bb * sbA + ss * slA + (long)(by * 128) * ldA;
    Bm += bb * sbB + ss * slB + (long)(bx * 64) * ldB;
    D  += bb * sbD + ss * slD;

    if (tid < 128) sBM[tid] = biasM ? biasM[by * 128 + tid] : 0.f;
    if (tid < 64)  sBN[tid] = biasN ? biasN[bx * 64 + tid] : 0.f;

    const int sf = tid & 7;
    const int sr = tid >> 3;
    const int nIter = K / 32;

    const float* pA[4];
    const float* pB[2];
#pragma unroll
    for (int i = 0; i < 4; ++i)
        pA[i] = A + (long)(sr + 32 * i) * ldA + sf * 4;
#pragma unroll
    for (int i = 0; i < 2; ++i)
        pB[i] = Bm + (long)(sr + 32 * i) * ldB + sf * 4;

    float4 ra[4], rb[2];
#pragma unroll
    for (int i = 0; i < 4; ++i) { ra[i] = *(const float4*)pA[i]; pA[i] += 32; }
#pragma unroll
    for (int i = 0; i < 2; ++i) { rb[i] = *(const float4*)pB[i]; pB[i] += 32; }
    {
        half* Ab = sh;
        half* Bb = sh + OFF_BH / 2;
#pragma unroll
        for (int i = 0; i < 4; ++i)
            split_store(Ab, (sr + 32 * i) * PITCH + sf * 4, ra[i]);
#pragma unroll
        for (int i = 0; i < 2; ++i)
            store_hi(Bb, (sr + 32 * i) * PITCH + sf * 4, rb[i]);
    }
    __syncthreads();

    float acc[2][4][4];
#pragma unroll
    for (int mi = 0; mi < 2; ++mi)
#pragma unroll
        for (int ni = 0; ni < 4; ++ni)
#pragma unroll
            for (int q = 0; q < 4; ++q) acc[mi][ni][q] = 0.f;

    const int wid = tid >> 5, lid = tid & 31;
    const int wm = (wid >> 1) * 32;
    const int wn = (wid & 1) * 32;
    const int g = lid >> 2;
    const int t = lid & 3;

    const uint32_t laneA = (uint32_t)((lid & 15) * ROWB + (lid >> 4) * 16);
    const uint32_t laneB = (uint32_t)((((lid >> 4) * 8) + (lid & 7)) * ROWB
                                      + ((lid >> 3) & 1) * 16);
    const uint32_t aWarp = sbu + (uint32_t)(wm * ROWB) + laneA;
    const uint32_t bWarp = sbu + OFF_BH + (uint32_t)(wn * ROWB) + laneB;

    for (int it = 0; it < nIter; ++it) {
        const int buf = it & 1;
        const bool hasNext = (it + 1 < nIter);
        if (hasNext) {
#pragma unroll
            for (int i = 0; i < 4; ++i) { ra[i] = *(const float4*)pA[i]; pA[i] += 32; }
#pragma unroll
            for (int i = 0; i < 2; ++i) { rb[i] = *(const float4*)pB[i]; pB[i] += 32; }
        }

        const uint32_t bo = (uint32_t)(buf * BUF_BYTES);
#pragma unroll
        for (int kk = 0; kk < 2; ++kk) {
            const uint32_t ko = (uint32_t)(kk * 32);
            uint32_t ah[2][4], al[2][4];
#pragma unroll
            for (int mi = 0; mi < 2; ++mi) {
                const uint32_t addr = aWarp + bo + (uint32_t)(mi * 16 * ROWB) + ko;
                ldm_x4(ah[mi], addr);
                ldm_x4(al[mi], addr + A_TILE_B);
            }
            uint32_t bh[2][4];
#pragma unroll
            for (int nb = 0; nb < 2; ++nb)
                ldm_x4(bh[nb], bWarp + bo + (uint32_t)(nb * 16 * ROWB) + ko);
#pragma unroll
            for (int mi = 0; mi < 2; ++mi)
#pragma unroll
                for (int ni = 0; ni < 4; ++ni)
                    mma16816(acc[mi][ni], ah[mi], &bh[ni >> 1][(ni & 1) * 2]);
#pragma unroll
            for (int mi = 0; mi < 2; ++mi)
#pragma unroll
                for (int ni = 0; ni < 4; ++ni)
                    mma16816(acc[mi][ni], al[mi], &bh[ni >> 1][(ni & 1) * 2]);
        }

        if (hasNext) {
            half* Ab = sh + (buf ^ 1) * (BUF_BYTES / 2);
            half* Bb = Ab + OFF_BH / 2;
#pragma unroll
            for (int i = 0; i < 4; ++i)
                split_store(Ab, (sr + 32 * i) * PITCH + sf * 4, ra[i]);
#pragma unroll
            for (int i = 0; i < 2; ++i)
                store_hi(Bb, (sr + 32 * i) * PITCH + sf * 4, rb[i]);
        }
        __syncthreads();
    }

    // epilogue
#pragma unroll
    for (int mi = 0; mi < 2; ++mi) {
        const int rowLoc = wm + mi * 16 + g;
        const int chan0 = by * 128 + rowLoc;
        const float bm0 = sBM[rowLoc], bm1 = sBM[rowLoc + 8];
        const long gr0 = (long)chan0 * Nt + bx * 64;
        const long gr1 = gr0 + 8L * Nt;
        float s0 = 0.f, q0 = 0.f, s1 = 0.f, q1 = 0.f;
#pragma unroll
        for (int ni = 0; ni < 4; ++ni) {
            const int col = wn + ni * 8 + t * 2;
            const float bn0 = sBN[col], bn1 = sBN[col + 1];
            float2 o0, o1;
            o0.x = alpha * acc[mi][ni][0] + bm0 + bn0;
            o0.y = alpha * acc[mi][ni][1] + bm0 + bn1;
            o1.x = alpha * acc[mi][ni][2] + bm1 + bn0;
            o1.y = alpha * acc[mi][ni][3] + bm1 + bn1;
            if (ATOMIC_OUT) {
                atomicAdd(&D[gr0 + col],     o0.x);
                atomicAdd(&D[gr0 + col + 1], o0.y);
                atomicAdd(&D[gr1 + col],     o1.x);
                atomicAdd(&D[gr1 + col + 1], o1.y);
            } else {
                *(float2*)&D[gr0 + col] = o0;
                *(float2*)&D[gr1 + col] = o1;
            }
            if (BN_ACC) {
                s0 += o0.x + o0.y;  q0 += o0.x * o0.x + o0.y * o0.y;
                s1 += o1.x + o1.y;  q1 += o1.x * o1.x + o1.y * o1.y;
            }
        }
        if (BN_ACC) {
#pragma unroll
            for (int o = 1; o < 4; o <<= 1) {
                s0 += __shfl_xor_sync(0xFFFFFFFF, s0, o);
                q0 += __shfl_xor_sync(0xFFFFFFFF, q0, o);
                s1 += __shfl_xor_sync(0xFFFFFFFF, s1, o);
                q1 += __shfl_xor_sync(0xFFFFFFFF, q1, o);
            }
            if (t == 0) {
                atomicAdd(&bn_sum[chan0],       s0);
                atomicAdd(&bn_sumsq[chan0],     q0);
                atomicAdd(&bn_sum[chan0 + 8],   s1);
                atomicAdd(&bn_sumsq[chan0 + 8], q1);
            }
        }
    }
}

// ------------------------------------------------------------------------------
// v [B,C,N] fp32 -> vT [B,N,C] fp16 hi
__global__ __launch_bounds__(256)
void transpose_h_kernel(const float* __restrict__ v, half* __restrict__ o)
{
    __shared__ float tbuf[32][33];
    const int b = blockIdx.z;
    const int n0 = blockIdx.x * 32, c0 = blockIdx.y * 32;
    const int tx = threadIdx.x, ty = threadIdx.y;   // 32 x 8
#pragma unroll
    for (int i = 0; i < 4; ++i)
        tbuf[ty + 8 * i][tx] = v[((long)b * C_ + c0 + ty + 8 * i) * N_ + n0 + tx];
    __syncthreads();
#pragma unroll
    for (int i = 0; i < 4; ++i)
        o[((long)b * N_ + n0 + ty + 8 * i) * C_ + c0 + tx] =
            __float2half_rn(tbuf[tx][ty + 8 * i]);
}

// ------------------------------------------------------------------------------
// weights fp32 -> fp16 hi (3 matrices); also zero Zt + BN accumulators
__global__ __launch_bounds__(256)
void prep_kernel(const float* __restrict__ Wph, const float* __restrict__ Wg,
                 const float* __restrict__ Wth,
                 half* __restrict__ dPh, half* __restrict__ dG, half* __restrict__ dTh,
                 float* __restrict__ Zt)
{
    const int i = blockIdx.x * 256 + threadIdx.x;   // float4 idx, 3*32768 = 98304
    const int q = CI_ * C_ / 4;
    const int m = i / q, j = i % q;
    const float* src = (m == 0) ? Wph : (m == 1) ? Wg : Wth;
    half* dst = (m == 0) ? dPh : (m == 1) ? dG : dTh;
    const float4 x = ((const float4*)src)[j];
    half2 h01 = __floats2half2_rn(x.x, x.y);
    half2 h23 = __floats2half2_rn(x.z, x.w);
    *(half2*)&dst[j * 4]     = h01;
    *(half2*)&dst[j * 4 + 2] = h23;
    if (i < B_ * CI_ * CI_) Zt[i] = 0.f;   // covers 262144 < 98304? no!
}

// Zt zero needs full coverage: separate kernel
__global__ __launch_bounds__(256)
void zero_kernel(float* __restrict__ Zt)
{
    const int i = blockIdx.x * 256 + threadIdx.x;
    Zt[i] = 0.f;
    if (i < C_) { bn_sum[i] = 0.f; bn_sumsq[i] = 0.f; }
}

// ------------------------------------------------------------------------------
__global__ __launch_bounds__(256)
void bn_apply_kernel(const float* __restrict__ Wy,
                     const float* __restrict__ v,
                     const float* __restrict__ gamma,
                     const float* __restrict__ beta,
                     float* __restrict__ out)
{
    const long idx = (long)blockIdx.x * 256 + threadIdx.x;
    const long total4 = (long)B_ * C_ * N_ / 4;
    if (idx >= total4) return;
    const int c = (int)((idx * 4 / N_) % C_);
    const float inv = 1.f / (float)(B_ * N_);
    const float mean = bn_sum[c] * inv;
    const float var  = fmaxf(bn_sumsq[c] * inv - mean * mean, 0.f);
    const float rstd = rsqrtf(var + EPS_);
    const float sc = rstd * gamma[c];
    const float sh = beta[c] - mean * sc;
    const float4 w  = ((const float4*)Wy)[idx];
    const float4 vv = ((const float4*)v)[idx];
    float4 o;
    o.x = w.x * sc + sh + vv.x;
    o.y = w.y * sc + sh + vv.y;
    o.z = w.z * sc + sh + vv.z;
    o.w = w.w * sc + sh + vv.w;
    ((float4*)out)[idx] = o;
}

// ------------------------------------------------------------------------------
#define SYM(p, s) cudaGetSymbolAddress((void**)&p, s)

extern "C" void kernel_launch(void* const* d_in, const int* in_sizes, int n_in,
                              void* d_out, int out_size)
{
    const float* v     = (const float*)d_in[0];
    const float* Wg    = (const float*)d_in[1];
    const float* bg    = (const float*)d_in[2];
    const float* Wth   = (const float*)d_in[3];
    const float* bth   = (const float*)d_in[4];
    const float* Wph   = (const float*)d_in[5];
    const float* bph   = (const float*)d_in[6];
    const float* Ww    = (const float*)d_in[7];
    const float* bw    = (const float*)d_in[8];
    const float* gamma = (const float*)d_in[9];
    const float* beta  = (const float*)d_in[10];
    float* out = (float*)d_out;

    half *vTh, *wphH, *wgH, *wthH;
    float *th, *ph, *g, *y, *Wy, *Zt;
    SYM(vTh, vT_h);
    SYM(wphH, WphH);  SYM(wgH, WgH);  SYM(wthH, WthH);
    SYM(th, th_buf);
    SYM(ph, ph_buf);
    SYM(g,  g_buf);
    SYM(y,  y_buf);
    SYM(Wy, Wy_buf);
    SYM(Zt, Zt_buf);

    cudaFuncSetAttribute(gemm_h1, cudaFuncAttributeMaxDynamicSharedMemorySize, SMEM_H1_BYTES);
    cudaFuncSetAttribute(gemm_fp16h<false, true >, cudaFuncAttributeMaxDynamicSharedMemorySize, SMEM_GEMM_BYTES);
    cudaFuncSetAttribute(gemm_fp16h<false, false>, cudaFuncAttributeMaxDynamicSharedMemorySize, SMEM_GEMM_BYTES);
    cudaFuncSetAttribute(gemm_fp16h<true,  false>, cudaFuncAttributeMaxDynamicSharedMemorySize, SMEM_GEMM_BYTES);

    const long sVT = (long)N_ * C_;    // vT batch stride (halves)
    const long sNC = (long)N_ * CI_;
    const long sCN = (long)CI_ * N_;
    const long sC  = (long)C_ * N_;
    const long sZ  = (long)CI_ * CI_;

    // 0) zero Zt + BN; convert weights; transpose v -> vT fp16
    zero_kernel<<<(B_ * CI_ * CI_) / 256, 256>>>(Zt);
    prep_kernel<<<(3 * CI_ * C_ / 4) / 256, 256>>>(Wph, Wg, Wth, wphH, wgH, wthH, Zt);
    transpose_h_kernel<<<dim3(N_ / 32, C_ / 32, B_), dim3(32, 8)>>>(v, vTh);

    // 1) ph[ci,n] = WphH . vTh^T + bph   (h1; biasM)
    gemm_h1<<<dim3(N_ / 64, CI_ / 128, B_), 256, SMEM_H1_BYTES>>>(
        wphH, vTh, ph, bph, nullptr, CI_, N_, C_, C_, C_, 0, sVT, sCN);
    // 2) g[ci,n] = WgH . vTh^T + bg      (h1)
    gemm_h1<<<dim3(N_ / 64, CI_ / 128, B_), 256, SMEM_H1_BYTES>>>(
        wgH, vTh, g, bg, nullptr, CI_, N_, C_, C_, C_, 0, sVT, sCN);
    // 3) Zt[cg,cth] += (ZSCALE/N) g . ph^T   (x2; split-K atomic; fp32 in)
    gemm_fp16h<false, true><<<dim3(CI_ / 64, CI_ / 128, B_ * SLICES), 256, SMEM_GEMM_BYTES>>>(
        g, ph, Zt, nullptr, nullptr, CI_, CI_, N_ / SLICES, N_, N_, ZSCALE / (float)N_,
        SLICES, sCN, N_ / SLICES, sCN, N_ / SLICES, sZ, 0);
    // 4) th[n,cth] = vTh . WthH^T + bth  (h1; biasN)
    gemm_h1<<<dim3(CI_ / 64, N_ / 128, B_), 256, SMEM_H1_BYTES>>>(
        vTh, wthH, th, nullptr, bth, N_, CI_, C_, C_, C_, sVT, 0, sNC);
    // 5) y[n,cg] = (1/ZSCALE) th . Zt^T  (x2; fp32 in)
    gemm_fp16h<false, false><<<dim3(CI_ / 64, N_ / 128, B_), 256, SMEM_GEMM_BYTES>>>(
        th, Zt, y, nullptr, nullptr, N_, CI_, CI_, CI_, CI_, 1.f / ZSCALE,
        1, sNC, 0, sZ, 0, sNC, 0);
    // 6) Wy[c,n] = Ww . y^T + bw         (x2; biasM; BN stats)
    gemm_fp16h<true, false><<<dim3(N_ / 64, C_ / 128, B_), 256, SMEM_GEMM_BYTES>>>(
        Ww, y, Wy, bw, nullptr, C_, N_, CI_, CI_, CI_, 1.f,
        1, 0, 0, sNC, 0, sC, 0);

    // 7) BN apply + affine + residual
    const long total4 = (long)B_ * C_ * N_ / 4;
    bn_apply_kernel<<<(int)((total4 + 255) / 256), 256>>>(Wy, v, gamma, beta, out);
}

// round 15
// speedup vs baseline: 1.3540x; 1.0671x over previous
#include <cuda_runtime.h>
#include <cuda_fp16.h>
#include <cstdint>

#define B_  4
#define C_  512
#define CI_ 256
#define N_  4096
#define EPS_ 1e-5f
#define ZSCALE 64.0f
#define SLICES 16

// ------------------------- device scratch (no allocs) -------------------------
__device__ half  vT_h [B_ * N_ * C_];                  // 16 MB [B,N,C]
__device__ half  WphH [CI_ * C_];
__device__ half  WgH  [CI_ * C_];
__device__ half  WthH [CI_ * C_];
__device__ half  WwH  [C_ * CI_];
__device__ half  ph_h [B_ * CI_ * N_];                 // 8 MB [B,Ci,N]
__device__ half  g_h  [B_ * CI_ * N_];                 // 8 MB [B,Ci,N]
__device__ half  th_h [B_ * N_ * CI_];                 // 8 MB [B,N,Ci]
__device__ half  y_h  [B_ * N_ * CI_];                 // 8 MB [B,N,Ci]
__device__ float Wy_buf[B_ * C_ * N_];                 // 32 MB [B,C,N]
__device__ float Zt_buf[B_ * CI_ * CI_];               //  1 MB [B,cg,cth]
__device__ float bn_sum[C_];
__device__ float bn_sumsq[C_];

// ------------------------------- GEMM config ----------------------------------
// CTA tile 128(M) x 64(N) x 32(K), 256 threads (8 warps, 4x2, 32x32 each).
// Single-pass fp16: A hi + B hi only.
#define PITCH 40                          // halves per smem row (80B), conflict-free
#define ROWB  (PITCH * 2)
#define A_TILE_B 10240                    // 128 rows * 80B
#define B_TILE_B 5120                     // 64 rows * 80B
#define OFF_BH1   A_TILE_B
#define BUF1_BYTES (A_TILE_B + B_TILE_B)  // 15360
#define SMEM_H1_BYTES (2 * BUF1_BYTES + 1024)   // 31744

__device__ __forceinline__ uint32_t smem_u32(const void* p) {
    uint32_t a;
    asm("{ .reg .u64 t; cvta.to.shared.u64 t, %1; cvt.u32.u64 %0, t; }" : "=r"(a) : "l"(p));
    return a;
}
__device__ __forceinline__ void ldm_x4(uint32_t* r, uint32_t addr) {
    asm volatile("ldmatrix.sync.aligned.m8n8.x4.shared.b16 {%0,%1,%2,%3}, [%4];"
                 : "=r"(r[0]), "=r"(r[1]), "=r"(r[2]), "=r"(r[3]) : "r"(addr));
}
__device__ __forceinline__ void mma16816(float* c, const uint32_t* a, const uint32_t* b) {
    asm volatile(
        "mma.sync.aligned.m16n8k16.row.col.f32.f16.f16.f32 "
        "{%0,%1,%2,%3}, {%4,%5,%6,%7}, {%8,%9}, {%0,%1,%2,%3};"
        : "+f"(c[0]), "+f"(c[1]), "+f"(c[2]), "+f"(c[3])
        : "r"(a[0]), "r"(a[1]), "r"(a[2]), "r"(a[3]), "r"(b[0]), "r"(b[1]));
}
__device__ __forceinline__ void store_hi(half* base, int idx, float4 x) {
    *(half2*)&base[idx]     = __floats2half2_rn(x.x, x.y);
    *(half2*)&base[idx + 2] = __floats2half2_rn(x.z, x.w);
}

// ==============================================================================
// Unified single-pass fp16 GEMM:
//   D[M,Nt] = alpha * A[M,K](fp16) @ B[Nt,K]^T + biasM + biasN
// A fp16 (ldA halves). B_F32=0: B fp16 (ldB halves). B_F32=1: B fp32 (ldB floats),
// converted to hi at staging.
// OUT_MODE: 0 = fp32 store, 1 = fp32 atomicAdd (split-K), 2 = fp32 store + BN
// accumulation, 3 = fp16 store.
// grid = (Nt/64, M/128, nBatch*nSlices); per-z: X += b*sbX + s*slX.
// ==============================================================================
template <int OUT_MODE, bool B_F32>
__global__ __launch_bounds__(256, 2)
void gemm_u(const half* __restrict__ A,
            const half* __restrict__ Bh, const float* __restrict__ Bf,
            float* __restrict__ Df, half* __restrict__ Dh,
            const float* __restrict__ biasM, const float* __restrict__ biasN,
            int M, int Nt, int K, int ldA, int ldB, float alpha,
            int nSlices,
            long sbA, long slA, long sbB, long slB, long sbD, long slD)
{
    extern __shared__ char smem[];
    half*  sh  = (half*)smem;
    float* sBM = (float*)(smem + 2 * BUF1_BYTES);
    float* sBN = sBM + 128;
    const uint32_t sbu = smem_u32(sh);

    const int tid = threadIdx.x;
    const int bx = blockIdx.x, by = blockIdx.y, bz = blockIdx.z;
    const int bb = bz / nSlices;
    const int ss = bz % nSlices;
    A += bb * sbA + ss * slA + (long)(by * 128) * ldA;
    if (B_F32) Bf += bb * sbB + ss * slB + (long)(bx * 64) * ldB;
    else       Bh += bb * sbB + ss * slB + (long)(bx * 64) * ldB;
    const long dOff = bb * sbD + ss * slD;

    if (tid < 128) sBM[tid] = biasM ? biasM[by * 128 + tid] : 0.f;
    if (tid < 64)  sBN[tid] = biasN ? biasN[bx * 64 + tid] : 0.f;

    const int sf = tid & 7;       // 4-half / float4 chunk
    const int sr = tid >> 3;      // 0..31 row base
    const int nIter = K / 32;

    const half* pA[4];
#pragma unroll
    for (int i = 0; i < 4; ++i)
        pA[i] = A + (long)(sr + 32 * i) * ldA + sf * 4;
    const half*  pBh[2];
    const float* pBf[2];
#pragma unroll
    for (int i = 0; i < 2; ++i) {
        if (B_F32) pBf[i] = Bf + (long)(sr + 32 * i) * ldB + sf * 4;
        else       pBh[i] = Bh + (long)(sr + 32 * i) * ldB + sf * 4;
    }

    uint2 ra[4], rbh[2];
    float4 rbf[2];
#pragma unroll
    for (int i = 0; i < 4; ++i) { ra[i] = *(const uint2*)pA[i]; pA[i] += 32; }
#pragma unroll
    for (int i = 0; i < 2; ++i) {
        if (B_F32) { rbf[i] = *(const float4*)pBf[i]; pBf[i] += 32; }
        else       { rbh[i] = *(const uint2*)pBh[i];  pBh[i] += 32; }
    }
    {
        half* Ab = sh;
        half* Bb = sh + OFF_BH1 / 2;
#pragma unroll
        for (int i = 0; i < 4; ++i)
            *(uint2*)&Ab[(sr + 32 * i) * PITCH + sf * 4] = ra[i];
#pragma unroll
        for (int i = 0; i < 2; ++i) {
            const int idx = (sr + 32 * i) * PITCH + sf * 4;
            if (B_F32) store_hi(Bb, idx, rbf[i]);
            else       *(uint2*)&Bb[idx] = rbh[i];
        }
    }
    __syncthreads();

    float acc[2][4][4];
#pragma unroll
    for (int mi = 0; mi < 2; ++mi)
#pragma unroll
        for (int ni = 0; ni < 4; ++ni)
#pragma unroll
            for (int q = 0; q < 4; ++q) acc[mi][ni][q] = 0.f;

    const int wid = tid >> 5, lid = tid & 31;
    const int wm = (wid >> 1) * 32;
    const int wn = (wid & 1) * 32;
    const int g = lid >> 2;
    const int t = lid & 3;

    const uint32_t laneA = (uint32_t)((lid & 15) * ROWB + (lid >> 4) * 16);
    const uint32_t laneB = (uint32_t)((((lid >> 4) * 8) + (lid & 7)) * ROWB
                                      + ((lid >> 3) & 1) * 16);
    const uint32_t aWarp = sbu + (uint32_t)(wm * ROWB) + laneA;
    const uint32_t bWarp = sbu + OFF_BH1 + (uint32_t)(wn * ROWB) + laneB;

    for (int it = 0; it < nIter; ++it) {
        const int buf = it & 1;
        const bool hasNext = (it + 1 < nIter);
        if (hasNext) {
#pragma unroll
            for (int i = 0; i < 4; ++i) { ra[i] = *(const uint2*)pA[i]; pA[i] += 32; }
#pragma unroll
            for (int i = 0; i < 2; ++i) {
                if (B_F32) { rbf[i] = *(const float4*)pBf[i]; pBf[i] += 32; }
                else       { rbh[i] = *(const uint2*)pBh[i];  pBh[i] += 32; }
            }
        }

        const uint32_t bo = (uint32_t)(buf * BUF1_BYTES);
#pragma unroll
        for (int kk = 0; kk < 2; ++kk) {
            const uint32_t ko = (uint32_t)(kk * 32);
            uint32_t ah[2][4];
#pragma unroll
            for (int mi = 0; mi < 2; ++mi)
                ldm_x4(ah[mi], aWarp + bo + (uint32_t)(mi * 16 * ROWB) + ko);
            uint32_t bh[2][4];
#pragma unroll
            for (int nb = 0; nb < 2; ++nb)
                ldm_x4(bh[nb], bWarp + bo + (uint32_t)(nb * 16 * ROWB) + ko);
#pragma unroll
            for (int mi = 0; mi < 2; ++mi)
#pragma unroll
                for (int ni = 0; ni < 4; ++ni)
                    mma16816(acc[mi][ni], ah[mi], &bh[ni >> 1][(ni & 1) * 2]);
        }

        if (hasNext) {
            half* Ab = sh + (buf ^ 1) * (BUF1_BYTES / 2);
            half* Bb = Ab + OFF_BH1 / 2;
#pragma unroll
            for (int i = 0; i < 4; ++i)
                *(uint2*)&Ab[(sr + 32 * i) * PITCH + sf * 4] = ra[i];
#pragma unroll
            for (int i = 0; i < 2; ++i) {
                const int idx = (sr + 32 * i) * PITCH + sf * 4;
                if (B_F32) store_hi(Bb, idx, rbf[i]);
                else       *(uint2*)&Bb[idx] = rbh[i];
            }
        }
        __syncthreads();
    }

    // ---------------- epilogue ----------------
#pragma unroll
    for (int mi = 0; mi < 2; ++mi) {
        const int rowLoc = wm + mi * 16 + g;
        const int chan0 = by * 128 + rowLoc;
        const float bm0 = sBM[rowLoc], bm1 = sBM[rowLoc + 8];
        const long gr0 = dOff + (long)chan0 * Nt + bx * 64;
        const long gr1 = gr0 + 8L * Nt;
        float s0 = 0.f, q0 = 0.f, s1 = 0.f, q1 = 0.f;
#pragma unroll
        for (int ni = 0; ni < 4; ++ni) {
            const int col = wn + ni * 8 + t * 2;
            const float bn0 = sBN[col], bn1 = sBN[col + 1];
            float2 o0, o1;
            o0.x = alpha * acc[mi][ni][0] + bm0 + bn0;
            o0.y = alpha * acc[mi][ni][1] + bm0 + bn1;
            o1.x = alpha * acc[mi][ni][2] + bm1 + bn0;
            o1.y = alpha * acc[mi][ni][3] + bm1 + bn1;
            if (OUT_MODE == 1) {
                atomicAdd(&Df[gr0 + col],     o0.x);
                atomicAdd(&Df[gr0 + col + 1], o0.y);
                atomicAdd(&Df[gr1 + col],     o1.x);
                atomicAdd(&Df[gr1 + col + 1], o1.y);
            } else if (OUT_MODE == 3) {
                *(half2*)&Dh[gr0 + col] = __floats2half2_rn(o0.x, o0.y);
                *(half2*)&Dh[gr1 + col] = __floats2half2_rn(o1.x, o1.y);
            } else {
                *(float2*)&Df[gr0 + col] = o0;
                *(float2*)&Df[gr1 + col] = o1;
            }
            if (OUT_MODE == 2) {
                s0 += o0.x + o0.y;  q0 += o0.x * o0.x + o0.y * o0.y;
                s1 += o1.x + o1.y;  q1 += o1.x * o1.x + o1.y * o1.y;
            }
        }
        if (OUT_MODE == 2) {
#pragma unroll
            for (int o = 1; o < 4; o <<= 1) {
                s0 += __shfl_xor_sync(0xFFFFFFFF, s0, o);
                q0 += __shfl_xor_sync(0xFFFFFFFF, q0, o);
                s1 += __shfl_xor_sync(0xFFFFFFFF, s1, o);
                q1 += __shfl_xor_sync(0xFFFFFFFF, q1, o);
            }
            if (t == 0) {
                atomicAdd(&bn_sum[chan0],       s0);
                atomicAdd(&bn_sumsq[chan0],     q0);
                atomicAdd(&bn_sum[chan0 + 8],   s1);
                atomicAdd(&bn_sumsq[chan0 + 8], q1);
            }
        }
    }
}

// ------------------------------------------------------------------------------
// v [B,C,N] fp32 -> vT [B,N,C] fp16
__global__ __launch_bounds__(256)
void transpose_h_kernel(const float* __restrict__ v, half* __restrict__ o)
{
    __shared__ float tbuf[32][33];
    const int b = blockIdx.z;
    const int n0 = blockIdx.x * 32, c0 = blockIdx.y * 32;
    const int tx = threadIdx.x, ty = threadIdx.y;   // 32 x 8
#pragma unroll
    for (int i = 0; i < 4; ++i)
        tbuf[ty + 8 * i][tx] = v[((long)b * C_ + c0 + ty + 8 * i) * N_ + n0 + tx];
    __syncthreads();
#pragma unroll
    for (int i = 0; i < 4; ++i)
        o[((long)b * N_ + n0 + ty + 8 * i) * C_ + c0 + tx] =
            __float2half_rn(tbuf[tx][ty + 8 * i]);
}

// ------------------------------------------------------------------------------
// convert 4 weight matrices fp32 -> fp16
__global__ __launch_bounds__(256)
void prep_kernel(const float* __restrict__ Wph, const float* __restrict__ Wg,
                 const float* __restrict__ Wth, const float* __restrict__ Ww,
                 half* __restrict__ dPh, half* __restrict__ dG,
                 half* __restrict__ dTh, half* __restrict__ dW)
{
    const int i = blockIdx.x * 256 + threadIdx.x;   // float4 idx, 4*32768 = 131072
    const int q = CI_ * C_ / 4;
    const int m = i / q, j = i % q;
    const float* src = (m == 0) ? Wph : (m == 1) ? Wg : (m == 2) ? Wth : Ww;
    half* dst = (m == 0) ? dPh : (m == 1) ? dG : (m == 2) ? dTh : dW;
    const float4 x = ((const float4*)src)[j];
    *(half2*)&dst[j * 4]     = __floats2half2_rn(x.x, x.y);
    *(half2*)&dst[j * 4 + 2] = __floats2half2_rn(x.z, x.w);
}

// ------------------------------------------------------------------------------
__global__ __launch_bounds__(256)
void zero_kernel(float* __restrict__ Zt)
{
    const int i = blockIdx.x * 256 + threadIdx.x;
    Zt[i] = 0.f;
    if (i < C_) { bn_sum[i] = 0.f; bn_sumsq[i] = 0.f; }
}

// ------------------------------------------------------------------------------
__global__ __launch_bounds__(256)
void bn_apply_kernel(const float* __restrict__ Wy,
                     const float* __restrict__ v,
                     const float* __restrict__ gamma,
                     const float* __restrict__ beta,
                     float* __restrict__ out)
{
    const long idx = (long)blockIdx.x * 256 + threadIdx.x;
    const long total4 = (long)B_ * C_ * N_ / 4;
    if (idx >= total4) return;
    const int c = (int)((idx * 4 / N_) % C_);
    const float inv = 1.f / (float)(B_ * N_);
    const float mean = bn_sum[c] * inv;
    const float var  = fmaxf(bn_sumsq[c] * inv - mean * mean, 0.f);
    const float rstd = rsqrtf(var + EPS_);
    const float sc = rstd * gamma[c];
    const float sh = beta[c] - mean * sc;
    const float4 w  = ((const float4*)Wy)[idx];
    const float4 vv = ((const float4*)v)[idx];
    float4 o;
    o.x = w.x * sc + sh + vv.x;
    o.y = w.y * sc + sh + vv.y;
    o.z = w.z * sc + sh + vv.z;
    o.w = w.w * sc + sh + vv.w;
    ((float4*)out)[idx] = o;
}

// ------------------------------------------------------------------------------
#define SYM(p, s) cudaGetSymbolAddress((void**)&p, s)

extern "C" void kernel_launch(void* const* d_in, const int* in_sizes, int n_in,
                              void* d_out, int out_size)
{
    const float* v     = (const float*)d_in[0];
    const float* Wg    = (const float*)d_in[1];
    const float* bg    = (const float*)d_in[2];
    const float* Wth   = (const float*)d_in[3];
    const float* bth   = (const float*)d_in[4];
    const float* Wph   = (const float*)d_in[5];
    const float* bph   = (const float*)d_in[6];
    const float* Ww    = (const float*)d_in[7];
    const float* bw    = (const float*)d_in[8];
    const float* gamma = (const float*)d_in[9];
    const float* beta  = (const float*)d_in[10];
    float* out = (float*)d_out;

    half *vTh, *wphH, *wgH, *wthH, *wwH, *ph, *g, *th, *y;
    float *Wy, *Zt;
    SYM(vTh, vT_h);
    SYM(wphH, WphH);  SYM(wgH, WgH);  SYM(wthH, WthH);  SYM(wwH, WwH);
    SYM(ph, ph_h);
    SYM(g,  g_h);
    SYM(th, th_h);
    SYM(y,  y_h);
    SYM(Wy, Wy_buf);
    SYM(Zt, Zt_buf);

    cudaFuncSetAttribute(gemm_u<3, false>, cudaFuncAttributeMaxDynamicSharedMemorySize, SMEM_H1_BYTES);
    cudaFuncSetAttribute(gemm_u<1, false>, cudaFuncAttributeMaxDynamicSharedMemorySize, SMEM_H1_BYTES);
    cudaFuncSetAttribute(gemm_u<3, true >, cudaFuncAttributeMaxDynamicSharedMemorySize, SMEM_H1_BYTES);
    cudaFuncSetAttribute(gemm_u<2, false>, cudaFuncAttributeMaxDynamicSharedMemorySize, SMEM_H1_BYTES);

    const long sVT = (long)N_ * C_;    // halves
    const long sNC = (long)N_ * CI_;   // halves
    const long sCN = (long)CI_ * N_;   // halves
    const long sC  = (long)C_ * N_;    // floats
    const long sZ  = (long)CI_ * CI_;  // floats

    // 0) zero Zt + BN; convert weights; transpose v -> vT fp16
    zero_kernel<<<(B_ * CI_ * CI_) / 256, 256>>>(Zt);
    prep_kernel<<<(4 * CI_ * C_ / 4) / 256, 256>>>(
        Wph, Wg, Wth, Ww, wphH, wgH, wthH, wwH);
    transpose_h_kernel<<<dim3(N_ / 32, C_ / 32, B_), dim3(32, 8)>>>(v, vTh);

    // 1) ph[ci,n] = WphH . vTh^T + bph   (fp16 out; biasM)
    gemm_u<3, false><<<dim3(N_ / 64, CI_ / 128, B_), 256, SMEM_H1_BYTES>>>(
        wphH, vTh, nullptr, nullptr, ph, bph, nullptr,
        CI_, N_, C_, C_, C_, 1.f, 1, 0, 0, sVT, 0, sCN, 0);
    // 2) g[ci,n] = WgH . vTh^T + bg
    gemm_u<3, false><<<dim3(N_ / 64, CI_ / 128, B_), 256, SMEM_H1_BYTES>>>(
        wgH, vTh, nullptr, nullptr, g, bg, nullptr,
        CI_, N_, C_, C_, C_, 1.f, 1, 0, 0, sVT, 0, sCN, 0);
    // 3) Zt[cg,cth] += (ZSCALE/N) g . ph^T   (split-K atomic fp32 out)
    gemm_u<1, false><<<dim3(CI_ / 64, CI_ / 128, B_ * SLICES), 256, SMEM_H1_BYTES>>>(
        g, ph, nullptr, Zt, nullptr, nullptr, nullptr,
        CI_, CI_, N_ / SLICES, N_, N_, ZSCALE / (float)N_,
        SLICES, sCN, N_ / SLICES, sCN, N_ / SLICES, sZ, 0);
    // 4) th[n,cth] = vTh . WthH^T + bth   (fp16 out; biasN)
    gemm_u<3, false><<<dim3(CI_ / 64, N_ / 128, B_), 256, SMEM_H1_BYTES>>>(
        vTh, wthH, nullptr, nullptr, th, nullptr, bth,
        N_, CI_, C_, C_, C_, 1.f, 1, sVT, 0, 0, 0, sNC, 0);
    // 5) y[n,cg] = (1/ZSCALE) th . Zt^T   (B fp32; fp16 out)
    gemm_u<3, true><<<dim3(CI_ / 64, N_ / 128, B_), 256, SMEM_H1_BYTES>>>(
        th, nullptr, Zt, nullptr, y, nullptr, nullptr,
        N_, CI_, CI_, CI_, CI_, 1.f / ZSCALE, 1, sNC, 0, sZ, 0, sNC, 0);
    // 6) Wy[c,n] = WwH . y^T + bw         (fp32 out + BN stats; biasM)
    gemm_u<2, false><<<dim3(N_ / 64, C_ / 128, B_), 256, SMEM_H1_BYTES>>>(
        wwH, y, nullptr, Wy, nullptr, bw, nullptr,
        C_, N_, CI_, CI_, CI_, 1.f, 1, 0, 0, sNC, 0, sC, 0);

    // 7) BN apply + affine + residual
    const long total4 = (long)B_ * C_ * N_ / 4;
    bn_apply_kernel<<<(int)((total4 + 255) / 256), 256>>>(Wy, v, gamma, beta, out);
}

// round 16
// speedup vs baseline: 1.6443x; 1.2144x over previous
#include <cuda_runtime.h>
#include <cuda_fp16.h>
#include <cstdint>

#define B_  4
#define C_  512
#define CI_ 256
#define N_  4096
#define EPS_ 1e-5f
#define ZSCALE 64.0f
#define SLICES 16

// ------------------------- device scratch (no allocs) -------------------------
__device__ half  vT_h [B_ * N_ * C_];                  // 16 MB [B,N,C]
__device__ half  WphH [CI_ * C_];
__device__ half  WgH  [CI_ * C_];
__device__ half  WthH [CI_ * C_];
__device__ half  WwH  [C_ * CI_];
__device__ half  ph_h [B_ * CI_ * N_];                 // 8 MB [B,Ci,N]
__device__ half  g_h  [B_ * CI_ * N_];                 // 8 MB [B,Ci,N]
__device__ half  th_h [B_ * N_ * CI_];                 // 8 MB [B,N,Ci]
__device__ half  y_h  [B_ * N_ * CI_];                 // 8 MB [B,N,Ci]
__device__ float Wy_buf[B_ * C_ * N_];                 // 32 MB [B,C,N]
__device__ float Zt_buf[B_ * CI_ * CI_];               //  1 MB [B,cg,cth]
__device__ float bn_sum[C_];
__device__ float bn_sumsq[C_];

// ------------------------------- GEMM config ----------------------------------
// CTA tile 128(M) x 128(N) x 32(K), 256 threads (8 warps in 2x4, 64x32 each).
// Single-pass fp16 (A hi, B hi). Double-buffered smem.
#define PITCH 40                          // halves per smem row (80B), conflict-free
#define ROWB  (PITCH * 2)
#define A_TILE_B 10240                    // 128 rows * 80B
#define B_TILE_B 10240                    // 128 rows * 80B
#define OFF_B     A_TILE_B
#define BUF_BYTES (A_TILE_B + B_TILE_B)   // 20480
#define SMEM_GEMM_BYTES (2 * BUF_BYTES + 1024)   // 41984

__device__ __forceinline__ uint32_t smem_u32(const void* p) {
    uint32_t a;
    asm("{ .reg .u64 t; cvta.to.shared.u64 t, %1; cvt.u32.u64 %0, t; }" : "=r"(a) : "l"(p));
    return a;
}
__device__ __forceinline__ void ldm_x4(uint32_t* r, uint32_t addr) {
    asm volatile("ldmatrix.sync.aligned.m8n8.x4.shared.b16 {%0,%1,%2,%3}, [%4];"
                 : "=r"(r[0]), "=r"(r[1]), "=r"(r[2]), "=r"(r[3]) : "r"(addr));
}
__device__ __forceinline__ void mma16816(float* c, const uint32_t* a, const uint32_t* b) {
    asm volatile(
        "mma.sync.aligned.m16n8k16.row.col.f32.f16.f16.f32 "
        "{%0,%1,%2,%3}, {%4,%5,%6,%7}, {%8,%9}, {%0,%1,%2,%3};"
        : "+f"(c[0]), "+f"(c[1]), "+f"(c[2]), "+f"(c[3])
        : "r"(a[0]), "r"(a[1]), "r"(a[2]), "r"(a[3]), "r"(b[0]), "r"(b[1]));
}
__device__ __forceinline__ void store_hi(half* base, int idx, float4 x) {
    *(half2*)&base[idx]     = __floats2half2_rn(x.x, x.y);
    *(half2*)&base[idx + 2] = __floats2half2_rn(x.z, x.w);
}

// ==============================================================================
// Unified single-pass fp16 GEMM, 128x128x32 tiles:
//   D[M,Nt] = alpha * A[M,K](fp16) @ B[Nt,K]^T + biasM + biasN
// A fp16 (ldA halves). B_F32=0: B fp16 (ldB halves). B_F32=1: B fp32 (ldB floats).
// OUT_MODE: 0 = fp32 store, 1 = fp32 atomicAdd (split-K), 2 = fp32 store + BN
// accumulation, 3 = fp16 store.
// grid = (Nt/128, M/128, nBatch*nSlices); per-z: X += b*sbX + s*slX.
// ==============================================================================
template <int OUT_MODE, bool B_F32>
__global__ __launch_bounds__(256)
void gemm_u(const half* __restrict__ A,
            const half* __restrict__ Bh, const float* __restrict__ Bf,
            float* __restrict__ Df, half* __restrict__ Dh,
            const float* __restrict__ biasM, const float* __restrict__ biasN,
            int M, int Nt, int K, int ldA, int ldB, float alpha,
            int nSlices,
            long sbA, long slA, long sbB, long slB, long sbD, long slD)
{
    extern __shared__ char smem[];
    half*  sh  = (half*)smem;
    float* sBM = (float*)(smem + 2 * BUF_BYTES);
    float* sBN = sBM + 128;
    const uint32_t sbu = smem_u32(sh);

    const int tid = threadIdx.x;
    const int bx = blockIdx.x, by = blockIdx.y, bz = blockIdx.z;
    const int bb = bz / nSlices;
    const int ss = bz % nSlices;
    A += bb * sbA + ss * slA + (long)(by * 128) * ldA;
    if (B_F32) Bf += bb * sbB + ss * slB + (long)(bx * 128) * ldB;
    else       Bh += bb * sbB + ss * slB + (long)(bx * 128) * ldB;
    const long dOff = bb * sbD + ss * slD;

    if (tid < 128) {
        sBM[tid] = biasM ? biasM[by * 128 + tid] : 0.f;
        sBN[tid] = biasN ? biasN[bx * 128 + tid] : 0.f;
    }

    const int sf = tid & 7;       // 4-half / float4 chunk
    const int sr = tid >> 3;      // 0..31 row base
    const int nIter = K / 32;

    const half* pA[4];
#pragma unroll
    for (int i = 0; i < 4; ++i)
        pA[i] = A + (long)(sr + 32 * i) * ldA + sf * 4;
    const half*  pBh[4];
    const float* pBf[4];
#pragma unroll
    for (int i = 0; i < 4; ++i) {
        if (B_F32) pBf[i] = Bf + (long)(sr + 32 * i) * ldB + sf * 4;
        else       pBh[i] = Bh + (long)(sr + 32 * i) * ldB + sf * 4;
    }

    uint2 ra[4], rbh[4];
    float4 rbf[4];
#pragma unroll
    for (int i = 0; i < 4; ++i) {
        ra[i] = *(const uint2*)pA[i]; pA[i] += 32;
        if (B_F32) { rbf[i] = *(const float4*)pBf[i]; pBf[i] += 32; }
        else       { rbh[i] = *(const uint2*)pBh[i];  pBh[i] += 32; }
    }
    {
        half* Ab = sh;
        half* Bb = sh + OFF_B / 2;
#pragma unroll
        for (int i = 0; i < 4; ++i) {
            const int idx = (sr + 32 * i) * PITCH + sf * 4;
            *(uint2*)&Ab[idx] = ra[i];
            if (B_F32) store_hi(Bb, idx, rbf[i]);
            else       *(uint2*)&Bb[idx] = rbh[i];
        }
    }
    __syncthreads();

    float acc[4][4][4];
#pragma unroll
    for (int mi = 0; mi < 4; ++mi)
#pragma unroll
        for (int ni = 0; ni < 4; ++ni)
#pragma unroll
            for (int q = 0; q < 4; ++q) acc[mi][ni][q] = 0.f;

    const int wid = tid >> 5, lid = tid & 31;
    const int wm = (wid >> 2) * 64;   // warp m offset: 0/64
    const int wn = (wid & 3) * 32;    // warp n offset: 0/32/64/96
    const int g = lid >> 2;
    const int t = lid & 3;

    const uint32_t laneA = (uint32_t)((lid & 15) * ROWB + (lid >> 4) * 16);
    const uint32_t laneB = (uint32_t)((((lid >> 4) * 8) + (lid & 7)) * ROWB
                                      + ((lid >> 3) & 1) * 16);
    const uint32_t aWarp = sbu + (uint32_t)(wm * ROWB) + laneA;
    const uint32_t bWarp = sbu + OFF_B + (uint32_t)(wn * ROWB) + laneB;

    for (int it = 0; it < nIter; ++it) {
        const int buf = it & 1;
        const bool hasNext = (it + 1 < nIter);
        if (hasNext) {
#pragma unroll
            for (int i = 0; i < 4; ++i) {
                ra[i] = *(const uint2*)pA[i]; pA[i] += 32;
                if (B_F32) { rbf[i] = *(const float4*)pBf[i]; pBf[i] += 32; }
                else       { rbh[i] = *(const uint2*)pBh[i];  pBh[i] += 32; }
            }
        }

        const uint32_t bo = (uint32_t)(buf * BUF_BYTES);
#pragma unroll
        for (int kk = 0; kk < 2; ++kk) {
            const uint32_t ko = (uint32_t)(kk * 32);
            uint32_t ah[4][4];
#pragma unroll
            for (int mi = 0; mi < 4; ++mi)
                ldm_x4(ah[mi], aWarp + bo + (uint32_t)(mi * 16 * ROWB) + ko);
            uint32_t bh[2][4];
#pragma unroll
            for (int nb = 0; nb < 2; ++nb)
                ldm_x4(bh[nb], bWarp + bo + (uint32_t)(nb * 16 * ROWB) + ko);
#pragma unroll
            for (int mi = 0; mi < 4; ++mi)
#pragma unroll
                for (int ni = 0; ni < 4; ++ni)
                    mma16816(acc[mi][ni], ah[mi], &bh[ni >> 1][(ni & 1) * 2]);
        }

        if (hasNext) {
            half* Ab = sh + (buf ^ 1) * (BUF_BYTES / 2);
            half* Bb = Ab + OFF_B / 2;
#pragma unroll
            for (int i = 0; i < 4; ++i) {
                const int idx = (sr + 32 * i) * PITCH + sf * 4;
                *(uint2*)&Ab[idx] = ra[i];
                if (B_F32) store_hi(Bb, idx, rbf[i]);
                else       *(uint2*)&Bb[idx] = rbh[i];
            }
        }
        __syncthreads();
    }

    // ---------------- epilogue ----------------
#pragma unroll
    for (int mi = 0; mi < 4; ++mi) {
        const int rowLoc = wm + mi * 16 + g;
        const int chan0 = by * 128 + rowLoc;
        const float bm0 = sBM[rowLoc], bm1 = sBM[rowLoc + 8];
        const long gr0 = dOff + (long)chan0 * Nt + bx * 128;
        const long gr1 = gr0 + 8L * Nt;
        float s0 = 0.f, q0 = 0.f, s1 = 0.f, q1 = 0.f;
#pragma unroll
        for (int ni = 0; ni < 4; ++ni) {
            const int col = wn + ni * 8 + t * 2;
            const float bn0 = sBN[col], bn1 = sBN[col + 1];
            float2 o0, o1;
            o0.x = alpha * acc[mi][ni][0] + bm0 + bn0;
            o0.y = alpha * acc[mi][ni][1] + bm0 + bn1;
            o1.x = alpha * acc[mi][ni][2] + bm1 + bn0;
            o1.y = alpha * acc[mi][ni][3] + bm1 + bn1;
            if (OUT_MODE == 1) {
                atomicAdd(&Df[gr0 + col],     o0.x);
                atomicAdd(&Df[gr0 + col + 1], o0.y);
                atomicAdd(&Df[gr1 + col],     o1.x);
                atomicAdd(&Df[gr1 + col + 1], o1.y);
            } else if (OUT_MODE == 3) {
                *(half2*)&Dh[gr0 + col] = __floats2half2_rn(o0.x, o0.y);
                *(half2*)&Dh[gr1 + col] = __floats2half2_rn(o1.x, o1.y);
            } else {
                *(float2*)&Df[gr0 + col] = o0;
                *(float2*)&Df[gr1 + col] = o1;
            }
            if (OUT_MODE == 2) {
                s0 += o0.x + o0.y;  q0 += o0.x * o0.x + o0.y * o0.y;
                s1 += o1.x + o1.y;  q1 += o1.x * o1.x + o1.y * o1.y;
            }
        }
        if (OUT_MODE == 2) {
#pragma unroll
            for (int o = 1; o < 4; o <<= 1) {
                s0 += __shfl_xor_sync(0xFFFFFFFF, s0, o);
                q0 += __shfl_xor_sync(0xFFFFFFFF, q0, o);
                s1 += __shfl_xor_sync(0xFFFFFFFF, s1, o);
                q1 += __shfl_xor_sync(0xFFFFFFFF, q1, o);
            }
            if (t == 0) {
                atomicAdd(&bn_sum[chan0],       s0);
                atomicAdd(&bn_sumsq[chan0],     q0);
                atomicAdd(&bn_sum[chan0 + 8],   s1);
                atomicAdd(&bn_sumsq[chan0 + 8], q1);
            }
        }
    }
}

// ------------------------------------------------------------------------------
// v [B,C,N] fp32 -> vT [B,N,C] fp16
__global__ __launch_bounds__(256)
void transpose_h_kernel(const float* __restrict__ v, half* __restrict__ o)
{
    __shared__ float tbuf[32][33];
    const int b = blockIdx.z;
    const int n0 = blockIdx.x * 32, c0 = blockIdx.y * 32;
    const int tx = threadIdx.x, ty = threadIdx.y;   // 32 x 8
#pragma unroll
    for (int i = 0; i < 4; ++i)
        tbuf[ty + 8 * i][tx] = v[((long)b * C_ + c0 + ty + 8 * i) * N_ + n0 + tx];
    __syncthreads();
#pragma unroll
    for (int i = 0; i < 4; ++i)
        o[((long)b * N_ + n0 + ty + 8 * i) * C_ + c0 + tx] =
            __float2half_rn(tbuf[tx][ty + 8 * i]);
}

// ------------------------------------------------------------------------------
// convert 4 weight matrices fp32 -> fp16
__global__ __launch_bounds__(256)
void prep_kernel(const float* __restrict__ Wph, const float* __restrict__ Wg,
                 const float* __restrict__ Wth, const float* __restrict__ Ww,
                 half* __restrict__ dPh, half* __restrict__ dG,
                 half* __restrict__ dTh, half* __restrict__ dW)
{
    const int i = blockIdx.x * 256 + threadIdx.x;   // float4 idx, 4*32768 = 131072
    const int q = CI_ * C_ / 4;
    const int m = i / q, j = i % q;
    const float* src = (m == 0) ? Wph : (m == 1) ? Wg : (m == 2) ? Wth : Ww;
    half* dst = (m == 0) ? dPh : (m == 1) ? dG : (m == 2) ? dTh : dW;
    const float4 x = ((const float4*)src)[j];
    *(half2*)&dst[j * 4]     = __floats2half2_rn(x.x, x.y);
    *(half2*)&dst[j * 4 + 2] = __floats2half2_rn(x.z, x.w);
}

// ------------------------------------------------------------------------------
__global__ __launch_bounds__(256)
void zero_kernel(float* __restrict__ Zt)
{
    const int i = blockIdx.x * 256 + threadIdx.x;
    Zt[i] = 0.f;
    if (i < C_) { bn_sum[i] = 0.f; bn_sumsq[i] = 0.f; }
}

// ------------------------------------------------------------------------------
__global__ __launch_bounds__(256)
void bn_apply_kernel(const float* __restrict__ Wy,
                     const float* __restrict__ v,
                     const float* __restrict__ gamma,
                     const float* __restrict__ beta,
                     float* __restrict__ out)
{
    const long idx = (long)blockIdx.x * 256 + threadIdx.x;
    const long total4 = (long)B_ * C_ * N_ / 4;
    if (idx >= total4) return;
    const int c = (int)((idx * 4 / N_) % C_);
    const float inv = 1.f / (float)(B_ * N_);
    const float mean = bn_sum[c] * inv;
    const float var  = fmaxf(bn_sumsq[c] * inv - mean * mean, 0.f);
    const float rstd = rsqrtf(var + EPS_);
    const float sc = rstd * gamma[c];
    const float sh = beta[c] - mean * sc;
    const float4 w  = ((const float4*)Wy)[idx];
    const float4 vv = ((const float4*)v)[idx];
    float4 o;
    o.x = w.x * sc + sh + vv.x;
    o.y = w.y * sc + sh + vv.y;
    o.z = w.z * sc + sh + vv.z;
    o.w = w.w * sc + sh + vv.w;
    ((float4*)out)[idx] = o;
}

// ------------------------------------------------------------------------------
#define SYM(p, s) cudaGetSymbolAddress((void**)&p, s)

extern "C" void kernel_launch(void* const* d_in, const int* in_sizes, int n_in,
                              void* d_out, int out_size)
{
    const float* v     = (const float*)d_in[0];
    const float* Wg    = (const float*)d_in[1];
    const float* bg    = (const float*)d_in[2];
    const float* Wth   = (const float*)d_in[3];
    const float* bth   = (const float*)d_in[4];
    const float* Wph   = (const float*)d_in[5];
    const float* bph   = (const float*)d_in[6];
    const float* Ww    = (const float*)d_in[7];
    const float* bw    = (const float*)d_in[8];
    const float* gamma = (const float*)d_in[9];
    const float* beta  = (const float*)d_in[10];
    float* out = (float*)d_out;

    half *vTh, *wphH, *wgH, *wthH, *wwH, *ph, *g, *th, *y;
    float *Wy, *Zt;
    SYM(vTh, vT_h);
    SYM(wphH, WphH);  SYM(wgH, WgH);  SYM(wthH, WthH);  SYM(wwH, WwH);
    SYM(ph, ph_h);
    SYM(g,  g_h);
    SYM(th, th_h);
    SYM(y,  y_h);
    SYM(Wy, Wy_buf);
    SYM(Zt, Zt_buf);

    cudaFuncSetAttribute(gemm_u<3, false>, cudaFuncAttributeMaxDynamicSharedMemorySize, SMEM_GEMM_BYTES);
    cudaFuncSetAttribute(gemm_u<1, false>, cudaFuncAttributeMaxDynamicSharedMemorySize, SMEM_GEMM_BYTES);
    cudaFuncSetAttribute(gemm_u<3, true >, cudaFuncAttributeMaxDynamicSharedMemorySize, SMEM_GEMM_BYTES);
    cudaFuncSetAttribute(gemm_u<2, false>, cudaFuncAttributeMaxDynamicSharedMemorySize, SMEM_GEMM_BYTES);

    const long sVT = (long)N_ * C_;    // halves
    const long sNC = (long)N_ * CI_;   // halves
    const long sCN = (long)CI_ * N_;   // halves
    const long sC  = (long)C_ * N_;    // floats
    const long sZ  = (long)CI_ * CI_;  // floats

    // 0) zero Zt + BN; convert weights; transpose v -> vT fp16
    zero_kernel<<<(B_ * CI_ * CI_) / 256, 256>>>(Zt);
    prep_kernel<<<(4 * CI_ * C_ / 4) / 256, 256>>>(
        Wph, Wg, Wth, Ww, wphH, wgH, wthH, wwH);
    transpose_h_kernel<<<dim3(N_ / 32, C_ / 32, B_), dim3(32, 8)>>>(v, vTh);

    // 1) ph[ci,n] = WphH . vTh^T + bph   (fp16 out; biasM)
    gemm_u<3, false><<<dim3(N_ / 128, CI_ / 128, B_), 256, SMEM_GEMM_BYTES>>>(
        wphH, vTh, nullptr, nullptr, ph, bph, nullptr,
        CI_, N_, C_, C_, C_, 1.f, 1, 0, 0, sVT, 0, sCN, 0);
    // 2) g[ci,n] = WgH . vTh^T + bg
    gemm_u<3, false><<<dim3(N_ / 128, CI_ / 128, B_), 256, SMEM_GEMM_BYTES>>>(
        wgH, vTh, nullptr, nullptr, g, bg, nullptr,
        CI_, N_, C_, C_, C_, 1.f, 1, 0, 0, sVT, 0, sCN, 0);
    // 3) Zt[cg,cth] += (ZSCALE/N) g . ph^T   (split-K atomic fp32 out)
    gemm_u<1, false><<<dim3(CI_ / 128, CI_ / 128, B_ * SLICES), 256, SMEM_GEMM_BYTES>>>(
        g, ph, nullptr, Zt, nullptr, nullptr, nullptr,
        CI_, CI_, N_ / SLICES, N_, N_, ZSCALE / (float)N_,
        SLICES, sCN, N_ / SLICES, sCN, N_ / SLICES, sZ, 0);
    // 4) th[n,cth] = vTh . WthH^T + bth   (fp16 out; biasN)
    gemm_u<3, false><<<dim3(CI_ / 128, N_ / 128, B_), 256, SMEM_GEMM_BYTES>>>(
        vTh, wthH, nullptr, nullptr, th, nullptr, bth,
        N_, CI_, C_, C_, C_, 1.f, 1, sVT, 0, 0, 0, sNC, 0);
    // 5) y[n,cg] = (1/ZSCALE) th . Zt^T   (B fp32; fp16 out)
    gemm_u<3, true><<<dim3(CI_ / 128, N_ / 128, B_), 256, SMEM_GEMM_BYTES>>>(
        th, nullptr, Zt, nullptr, y, nullptr, nullptr,
        N_, CI_, CI_, CI_, CI_, 1.f / ZSCALE, 1, sNC, 0, sZ, 0, sNC, 0);
    // 6) Wy[c,n] = WwH . y^T + bw         (fp32 out + BN stats; biasM)
    gemm_u<2, false><<<dim3(N_ / 128, C_ / 128, B_), 256, SMEM_GEMM_BYTES>>>(
        wwH, y, nullptr, Wy, nullptr, bw, nullptr,
        C_, N_, CI_, CI_, CI_, 1.f, 1, 0, 0, sNC, 0, sC, 0);

    // 7) BN apply + affine + residual
    const long total4 = (long)B_ * C_ * N_ / 4;
    bn_apply_kernel<<<(int)((total4 + 255) / 256), 256>>>(Wy, v, gamma, beta, out);
}

// round 17
// speedup vs baseline: 1.7113x; 1.0407x over previous
#include <cuda_runtime.h>
#include <cuda_fp16.h>
#include <cstdint>

#define B_  4
#define C_  512
#define CI_ 256
#define N_  4096
#define EPS_ 1e-5f
#define ZSCALE 64.0f
#define SLICES 16

// ------------------------- device scratch (no allocs) -------------------------
__device__ half  vT_h [B_ * N_ * C_];                  // 16 MB [B,N,C]
__device__ half  WphH [CI_ * C_];
__device__ half  WgH  [CI_ * C_];
__device__ half  WthH [CI_ * C_];
__device__ half  WwH  [C_ * CI_];
__device__ half  ph_h [B_ * CI_ * N_];                 // 8 MB [B,Ci,N]
__device__ half  g_h  [B_ * CI_ * N_];                 // 8 MB [B,Ci,N]
__device__ half  th_h [B_ * N_ * CI_];                 // 8 MB [B,N,Ci]
__device__ half  y_h  [B_ * N_ * CI_];                 // 8 MB [B,N,Ci]
__device__ float Wy_buf[B_ * C_ * N_];                 // 32 MB [B,C,N]
__device__ float Zt_buf[B_ * CI_ * CI_];               //  1 MB [B,cg,cth]
__device__ float bn_sum[C_];
__device__ float bn_sumsq[C_];

// ------------------------------- GEMM config ----------------------------------
// CTA tile 128(M) x 256(N) x 32(K), 256 threads (8 warps in 2x4, 64x64 each).
// Single-pass fp16 (A hi, B hi). Double-buffered smem.
#define PITCH 40                          // halves per smem row (80B), conflict-free
#define ROWB  (PITCH * 2)
#define A_TILE_B 10240                    // 128 rows * 80B
#define B_TILE_B 20480                    // 256 rows * 80B
#define OFF_B     A_TILE_B
#define BUF_BYTES (A_TILE_B + B_TILE_B)   // 30720
#define SMEM_GEMM_BYTES (2 * BUF_BYTES + 2048)   // 63488

__device__ __forceinline__ uint32_t smem_u32(const void* p) {
    uint32_t a;
    asm("{ .reg .u64 t; cvta.to.shared.u64 t, %1; cvt.u32.u64 %0, t; }" : "=r"(a) : "l"(p));
    return a;
}
__device__ __forceinline__ void ldm_x4(uint32_t* r, uint32_t addr) {
    asm volatile("ldmatrix.sync.aligned.m8n8.x4.shared.b16 {%0,%1,%2,%3}, [%4];"
                 : "=r"(r[0]), "=r"(r[1]), "=r"(r[2]), "=r"(r[3]) : "r"(addr));
}
__device__ __forceinline__ void mma16816(float* c, const uint32_t* a, const uint32_t* b) {
    asm volatile(
        "mma.sync.aligned.m16n8k16.row.col.f32.f16.f16.f32 "
        "{%0,%1,%2,%3}, {%4,%5,%6,%7}, {%8,%9}, {%0,%1,%2,%3};"
        : "+f"(c[0]), "+f"(c[1]), "+f"(c[2]), "+f"(c[3])
        : "r"(a[0]), "r"(a[1]), "r"(a[2]), "r"(a[3]), "r"(b[0]), "r"(b[1]));
}
__device__ __forceinline__ void store_hi(half* base, int idx, float4 x) {
    *(half2*)&base[idx]     = __floats2half2_rn(x.x, x.y);
    *(half2*)&base[idx + 2] = __floats2half2_rn(x.z, x.w);
}

// ==============================================================================
// Unified single-pass fp16 GEMM, 128x256x32 tiles:
//   D[M,Nt] = alpha * A[M,K](fp16) @ B[Nt,K]^T + biasM + biasN
// A fp16 (ldA halves). B_F32=0: B fp16 (ldB halves). B_F32=1: B fp32 (ldB floats).
// OUT_MODE: 0 = fp32 store, 1 = fp32 atomicAdd (split-K), 2 = fp32 store + BN
// accumulation, 3 = fp16 store.
// grid = (Nt/256, M/128, nBatch*nSlices); per-z: X += b*sbX + s*slX.
// ==============================================================================
template <int OUT_MODE, bool B_F32>
__global__ __launch_bounds__(256, 1)
void gemm_u(const half* __restrict__ A,
            const half* __restrict__ Bh, const float* __restrict__ Bf,
            float* __restrict__ Df, half* __restrict__ Dh,
            const float* __restrict__ biasM, const float* __restrict__ biasN,
            int M, int Nt, int K, int ldA, int ldB, float alpha,
            int nSlices,
            long sbA, long slA, long sbB, long slB, long sbD, long slD)
{
    extern __shared__ char smem[];
    half*  sh  = (half*)smem;
    float* sBM = (float*)(smem + 2 * BUF_BYTES);
    float* sBN = sBM + 128;
    const uint32_t sbu = smem_u32(sh);

    const int tid = threadIdx.x;
    const int bx = blockIdx.x, by = blockIdx.y, bz = blockIdx.z;
    const int bb = bz / nSlices;
    const int ss = bz % nSlices;
    A += bb * sbA + ss * slA + (long)(by * 128) * ldA;
    if (B_F32) Bf += bb * sbB + ss * slB + (long)(bx * 256) * ldB;
    else       Bh += bb * sbB + ss * slB + (long)(bx * 256) * ldB;
    const long dOff = bb * sbD + ss * slD;

    if (tid < 128) sBM[tid] = biasM ? biasM[by * 128 + tid] : 0.f;
    sBN[tid] = biasN ? biasN[bx * 256 + tid] : 0.f;

    const int sf = tid & 7;       // 4-half / float4 chunk
    const int sr = tid >> 3;      // 0..31 row base
    const int nIter = K / 32;

    const half* pA[4];
#pragma unroll
    for (int i = 0; i < 4; ++i)
        pA[i] = A + (long)(sr + 32 * i) * ldA + sf * 4;
    const half*  pBh[8];
    const float* pBf[8];
#pragma unroll
    for (int i = 0; i < 8; ++i) {
        if (B_F32) pBf[i] = Bf + (long)(sr + 32 * i) * ldB + sf * 4;
        else       pBh[i] = Bh + (long)(sr + 32 * i) * ldB + sf * 4;
    }

    uint2 ra[4], rbh[8];
    float4 rbf[8];
#pragma unroll
    for (int i = 0; i < 4; ++i) { ra[i] = *(const uint2*)pA[i]; pA[i] += 32; }
#pragma unroll
    for (int i = 0; i < 8; ++i) {
        if (B_F32) { rbf[i] = *(const float4*)pBf[i]; pBf[i] += 32; }
        else       { rbh[i] = *(const uint2*)pBh[i];  pBh[i] += 32; }
    }
    {
        half* Ab = sh;
        half* Bb = sh + OFF_B / 2;
#pragma unroll
        for (int i = 0; i < 4; ++i)
            *(uint2*)&Ab[(sr + 32 * i) * PITCH + sf * 4] = ra[i];
#pragma unroll
        for (int i = 0; i < 8; ++i) {
            const int idx = (sr + 32 * i) * PITCH + sf * 4;
            if (B_F32) store_hi(Bb, idx, rbf[i]);
            else       *(uint2*)&Bb[idx] = rbh[i];
        }
    }
    __syncthreads();

    float acc[4][8][4];
#pragma unroll
    for (int mi = 0; mi < 4; ++mi)
#pragma unroll
        for (int ni = 0; ni < 8; ++ni)
#pragma unroll
            for (int q = 0; q < 4; ++q) acc[mi][ni][q] = 0.f;

    const int wid = tid >> 5, lid = tid & 31;
    const int wm = (wid >> 2) * 64;   // warp m offset: 0/64
    const int wn = (wid & 3) * 64;    // warp n offset: 0/64/128/192
    const int g = lid >> 2;
    const int t = lid & 3;

    const uint32_t laneA = (uint32_t)((lid & 15) * ROWB + (lid >> 4) * 16);
    const uint32_t laneB = (uint32_t)((((lid >> 4) * 8) + (lid & 7)) * ROWB
                                      + ((lid >> 3) & 1) * 16);
    const uint32_t aWarp = sbu + (uint32_t)(wm * ROWB) + laneA;
    const uint32_t bWarp = sbu + OFF_B + (uint32_t)(wn * ROWB) + laneB;

    for (int it = 0; it < nIter; ++it) {
        const int buf = it & 1;
        const bool hasNext = (it + 1 < nIter);
        if (hasNext) {
#pragma unroll
            for (int i = 0; i < 4; ++i) { ra[i] = *(const uint2*)pA[i]; pA[i] += 32; }
#pragma unroll
            for (int i = 0; i < 8; ++i) {
                if (B_F32) { rbf[i] = *(const float4*)pBf[i]; pBf[i] += 32; }
                else       { rbh[i] = *(const uint2*)pBh[i];  pBh[i] += 32; }
            }
        }

        const uint32_t bo = (uint32_t)(buf * BUF_BYTES);
#pragma unroll
        for (int kk = 0; kk < 2; ++kk) {
            const uint32_t ko = (uint32_t)(kk * 32);
            uint32_t ah[4][4];
#pragma unroll
            for (int mi = 0; mi < 4; ++mi)
                ldm_x4(ah[mi], aWarp + bo + (uint32_t)(mi * 16 * ROWB) + ko);
            uint32_t bh[4][4];
#pragma unroll
            for (int nb = 0; nb < 4; ++nb)
                ldm_x4(bh[nb], bWarp + bo + (uint32_t)(nb * 16 * ROWB) + ko);
#pragma unroll
            for (int mi = 0; mi < 4; ++mi)
#pragma unroll
                for (int ni = 0; ni < 8; ++ni)
                    mma16816(acc[mi][ni], ah[mi], &bh[ni >> 1][(ni & 1) * 2]);
        }

        if (hasNext) {
            half* Ab = sh + (buf ^ 1) * (BUF_BYTES / 2);
            half* Bb = Ab + OFF_B / 2;
#pragma unroll
            for (int i = 0; i < 4; ++i)
                *(uint2*)&Ab[(sr + 32 * i) * PITCH + sf * 4] = ra[i];
#pragma unroll
            for (int i = 0; i < 8; ++i) {
                const int idx = (sr + 32 * i) * PITCH + sf * 4;
                if (B_F32) store_hi(Bb, idx, rbf[i]);
                else       *(uint2*)&Bb[idx] = rbh[i];
            }
        }
        __syncthreads();
    }

    // ---------------- epilogue ----------------
#pragma unroll
    for (int mi = 0; mi < 4; ++mi) {
        const int rowLoc = wm + mi * 16 + g;
        const int chan0 = by * 128 + rowLoc;
        const float bm0 = sBM[rowLoc], bm1 = sBM[rowLoc + 8];
        const long gr0 = dOff + (long)chan0 * Nt + bx * 256;
        const long gr1 = gr0 + 8L * Nt;
        float s0 = 0.f, q0 = 0.f, s1 = 0.f, q1 = 0.f;
#pragma unroll
        for (int ni = 0; ni < 8; ++ni) {
            const int col = wn + ni * 8 + t * 2;
            const float bn0 = sBN[col], bn1 = sBN[col + 1];
            float2 o0, o1;
            o0.x = alpha * acc[mi][ni][0] + bm0 + bn0;
            o0.y = alpha * acc[mi][ni][1] + bm0 + bn1;
            o1.x = alpha * acc[mi][ni][2] + bm1 + bn0;
            o1.y = alpha * acc[mi][ni][3] + bm1 + bn1;
            if (OUT_MODE == 1) {
                atomicAdd(&Df[gr0 + col],     o0.x);
                atomicAdd(&Df[gr0 + col + 1], o0.y);
                atomicAdd(&Df[gr1 + col],     o1.x);
                atomicAdd(&Df[gr1 + col + 1], o1.y);
            } else if (OUT_MODE == 3) {
                *(half2*)&Dh[gr0 + col] = __floats2half2_rn(o0.x, o0.y);
                *(half2*)&Dh[gr1 + col] = __floats2half2_rn(o1.x, o1.y);
            } else {
                *(float2*)&Df[gr0 + col] = o0;
                *(float2*)&Df[gr1 + col] = o1;
            }
            if (OUT_MODE == 2) {
                s0 += o0.x + o0.y;  q0 += o0.x * o0.x + o0.y * o0.y;
                s1 += o1.x + o1.y;  q1 += o1.x * o1.x + o1.y * o1.y;
            }
        }
        if (OUT_MODE == 2) {
#pragma unroll
            for (int o = 1; o < 4; o <<= 1) {
                s0 += __shfl_xor_sync(0xFFFFFFFF, s0, o);
                q0 += __shfl_xor_sync(0xFFFFFFFF, q0, o);
                s1 += __shfl_xor_sync(0xFFFFFFFF, s1, o);
                q1 += __shfl_xor_sync(0xFFFFFFFF, q1, o);
            }
            if (t == 0) {
                atomicAdd(&bn_sum[chan0],       s0);
                atomicAdd(&bn_sumsq[chan0],     q0);
                atomicAdd(&bn_sum[chan0 + 8],   s1);
                atomicAdd(&bn_sumsq[chan0 + 8], q1);
            }
        }
    }
}

// ------------------------------------------------------------------------------
// v [B,C,N] fp32 -> vT [B,N,C] fp16
__global__ __launch_bounds__(256)
void transpose_h_kernel(const float* __restrict__ v, half* __restrict__ o)
{
    __shared__ float tbuf[32][33];
    const int b = blockIdx.z;
    const int n0 = blockIdx.x * 32, c0 = blockIdx.y * 32;
    const int tx = threadIdx.x, ty = threadIdx.y;   // 32 x 8
#pragma unroll
    for (int i = 0; i < 4; ++i)
        tbuf[ty + 8 * i][tx] = v[((long)b * C_ + c0 + ty + 8 * i) * N_ + n0 + tx];
    __syncthreads();
#pragma unroll
    for (int i = 0; i < 4; ++i)
        o[((long)b * N_ + n0 + ty + 8 * i) * C_ + c0 + tx] =
            __float2half_rn(tbuf[tx][ty + 8 * i]);
}

// ------------------------------------------------------------------------------
// convert 4 weight matrices fp32 -> fp16
__global__ __launch_bounds__(256)
void prep_kernel(const float* __restrict__ Wph, const float* __restrict__ Wg,
                 const float* __restrict__ Wth, const float* __restrict__ Ww,
                 half* __restrict__ dPh, half* __restrict__ dG,
                 half* __restrict__ dTh, half* __restrict__ dW)
{
    const int i = blockIdx.x * 256 + threadIdx.x;   // float4 idx, 4*32768 = 131072
    const int q = CI_ * C_ / 4;
    const int m = i / q, j = i % q;
    const float* src = (m == 0) ? Wph : (m == 1) ? Wg : (m == 2) ? Wth : Ww;
    half* dst = (m == 0) ? dPh : (m == 1) ? dG : (m == 2) ? dTh : dW;
    const float4 x = ((const float4*)src)[j];
    *(half2*)&dst[j * 4]     = __floats2half2_rn(x.x, x.y);
    *(half2*)&dst[j * 4 + 2] = __floats2half2_rn(x.z, x.w);
}

// ------------------------------------------------------------------------------
__global__ __launch_bounds__(256)
void zero_kernel(float* __restrict__ Zt)
{
    const int i = blockIdx.x * 256 + threadIdx.x;
    Zt[i] = 0.f;
    if (i < C_) { bn_sum[i] = 0.f; bn_sumsq[i] = 0.f; }
}

// ------------------------------------------------------------------------------
__global__ __launch_bounds__(256)
void bn_apply_kernel(const float* __restrict__ Wy,
                     const float* __restrict__ v,
                     const float* __restrict__ gamma,
                     const float* __restrict__ beta,
                     float* __restrict__ out)
{
    const long idx = (long)blockIdx.x * 256 + threadIdx.x;
    const long total4 = (long)B_ * C_ * N_ / 4;
    if (idx >= total4) return;
    const int c = (int)((idx * 4 / N_) % C_);
    const float inv = 1.f / (float)(B_ * N_);
    const float mean = bn_sum[c] * inv;
    const float var  = fmaxf(bn_sumsq[c] * inv - mean * mean, 0.f);
    const float rstd = rsqrtf(var + EPS_);
    const float sc = rstd * gamma[c];
    const float sh = beta[c] - mean * sc;
    const float4 w  = ((const float4*)Wy)[idx];
    const float4 vv = ((const float4*)v)[idx];
    float4 o;
    o.x = w.x * sc + sh + vv.x;
    o.y = w.y * sc + sh + vv.y;
    o.z = w.z * sc + sh + vv.z;
    o.w = w.w * sc + sh + vv.w;
    ((float4*)out)[idx] = o;
}

// ------------------------------------------------------------------------------
#define SYM(p, s) cudaGetSymbolAddress((void**)&p, s)

extern "C" void kernel_launch(void* const* d_in, const int* in_sizes, int n_in,
                              void* d_out, int out_size)
{
    const float* v     = (const float*)d_in[0];
    const float* Wg    = (const float*)d_in[1];
    const float* bg    = (const float*)d_in[2];
    const float* Wth   = (const float*)d_in[3];
    const float* bth   = (const float*)d_in[4];
    const float* Wph   = (const float*)d_in[5];
    const float* bph   = (const float*)d_in[6];
    const float* Ww    = (const float*)d_in[7];
    const float* bw    = (const float*)d_in[8];
    const float* gamma = (const float*)d_in[9];
    const float* beta  = (const float*)d_in[10];
    float* out = (float*)d_out;

    half *vTh, *wphH, *wgH, *wthH, *wwH, *ph, *g, *th, *y;
    float *Wy, *Zt;
    SYM(vTh, vT_h);
    SYM(wphH, WphH);  SYM(wgH, WgH);  SYM(wthH, WthH);  SYM(wwH, WwH);
    SYM(ph, ph_h);
    SYM(g,  g_h);
    SYM(th, th_h);
    SYM(y,  y_h);
    SYM(Wy, Wy_buf);
    SYM(Zt, Zt_buf);

    cudaFuncSetAttribute(gemm_u<3, false>, cudaFuncAttributeMaxDynamicSharedMemorySize, SMEM_GEMM_BYTES);
    cudaFuncSetAttribute(gemm_u<1, false>, cudaFuncAttributeMaxDynamicSharedMemorySize, SMEM_GEMM_BYTES);
    cudaFuncSetAttribute(gemm_u<3, true >, cudaFuncAttributeMaxDynamicSharedMemorySize, SMEM_GEMM_BYTES);
    cudaFuncSetAttribute(gemm_u<2, false>, cudaFuncAttributeMaxDynamicSharedMemorySize, SMEM_GEMM_BYTES);

    const long sVT = (long)N_ * C_;    // halves
    const long sNC = (long)N_ * CI_;   // halves
    const long sCN = (long)CI_ * N_;   // halves
    const long sC  = (long)C_ * N_;    // floats
    const long sZ  = (long)CI_ * CI_;  // floats

    // 0) zero Zt + BN; convert weights; transpose v -> vT fp16
    zero_kernel<<<(B_ * CI_ * CI_) / 256, 256>>>(Zt);
    prep_kernel<<<(4 * CI_ * C_ / 4) / 256, 256>>>(
        Wph, Wg, Wth, Ww, wphH, wgH, wthH, wwH);
    transpose_h_kernel<<<dim3(N_ / 32, C_ / 32, B_), dim3(32, 8)>>>(v, vTh);

    // 1) ph[ci,n] = WphH . vTh^T + bph   (fp16 out; biasM)
    gemm_u<3, false><<<dim3(N_ / 256, CI_ / 128, B_), 256, SMEM_GEMM_BYTES>>>(
        wphH, vTh, nullptr, nullptr, ph, bph, nullptr,
        CI_, N_, C_, C_, C_, 1.f, 1, 0, 0, sVT, 0, sCN, 0);
    // 2) g[ci,n] = WgH . vTh^T + bg
    gemm_u<3, false><<<dim3(N_ / 256, CI_ / 128, B_), 256, SMEM_GEMM_BYTES>>>(
        wgH, vTh, nullptr, nullptr, g, bg, nullptr,
        CI_, N_, C_, C_, C_, 1.f, 1, 0, 0, sVT, 0, sCN, 0);
    // 3) Zt[cg,cth] += (ZSCALE/N) g . ph^T   (split-K atomic fp32 out)
    gemm_u<1, false><<<dim3(CI_ / 256, CI_ / 128, B_ * SLICES), 256, SMEM_GEMM_BYTES>>>(
        g, ph, nullptr, Zt, nullptr, nullptr, nullptr,
        CI_, CI_, N_ / SLICES, N_, N_, ZSCALE / (float)N_,
        SLICES, sCN, N_ / SLICES, sCN, N_ / SLICES, sZ, 0);
    // 4) th[n,cth] = vTh . WthH^T + bth   (fp16 out; biasN)
    gemm_u<3, false><<<dim3(CI_ / 256, N_ / 128, B_), 256, SMEM_GEMM_BYTES>>>(
        vTh, wthH, nullptr, nullptr, th, nullptr, bth,
        N_, CI_, C_, C_, C_, 1.f, 1, sVT, 0, 0, 0, sNC, 0);
    // 5) y[n,cg] = (1/ZSCALE) th . Zt^T   (B fp32; fp16 out)
    gemm_u<3, true><<<dim3(CI_ / 256, N_ / 128, B_), 256, SMEM_GEMM_BYTES>>>(
        th, nullptr, Zt, nullptr, y, nullptr, nullptr,
        N_, CI_, CI_, CI_, CI_, 1.f / ZSCALE, 1, sNC, 0, sZ, 0, sNC, 0);
    // 6) Wy[c,n] = WwH . y^T + bw         (fp32 out + BN stats; biasM)
    gemm_u<2, false><<<dim3(N_ / 256, C_ / 128, B_), 256, SMEM_GEMM_BYTES>>>(
        wwH, y, nullptr, Wy, nullptr, bw, nullptr,
        C_, N_, CI_, CI_, CI_, 1.f, 1, 0, 0, sNC, 0, sC, 0);

    // 7) BN apply + affine + residual
    const long total4 = (long)B_ * C_ * N_ / 4;
    bn_apply_kernel<<<(int)((total4 + 255) / 256), 256>>>(Wy, v, gamma, beta, out);
}